// round 9
// baseline (speedup 1.0000x reference)
#include <cuda_runtime.h>
#include <math.h>

#define B 128
#define N 996
#define BN (B*N)
#define DIM 16
#define QKD 128
#define GSZ 256
#define NG 4
#define DEPTH 8
#define VOC 1024
#define ROTD 32

// ---------------- scratch ----------------
__device__ __align__(16) float g_x[BN*DIM];
__device__ __align__(16) float g_qo[BN*32];          // ungated quad attention out
__device__ __align__(16) float g_linkvp[B*8*128*32];
__device__ float g_rc[N*16];
__device__ float g_rs[N*16];
__device__ float g_hmax[BN];

#define ROT_LC 0.57564627324851142
#define POS_LC 1.1512925464970228

typedef unsigned long long ull;

__device__ __forceinline__ ull pk2(float a, float b) {
    ull r; asm("mov.b64 %0,{%1,%2};" : "=l"(r) : "f"(a), "f"(b)); return r;
}
__device__ __forceinline__ void fma2(ull& d, ull a, ull b) {
    asm("fma.rn.f32x2 %0,%1,%2,%0;" : "+l"(d) : "l"(a), "l"(b));
}
__device__ __forceinline__ float2 up2(ull v) {
    float2 f; asm("mov.b64 {%0,%1},%2;" : "=f"(f.x), "=f"(f.y) : "l"(v)); return f;
}
__device__ __forceinline__ float silu_f(float a) {
    return __fdividef(a, 1.0f + __expf(-a));
}

// proj 8 outputs [u0,u0+8) ; nmA = prev-token normed d0..7, nmB = cur normed d8..15
__device__ __forceinline__ void proj8(const float* nmA, const float* nmB,
                                      const float* __restrict__ W, int ws,
                                      const float* __restrict__ bias, int u0, float* o) {
    #pragma unroll
    for (int j = 0; j < 8; j++) o[j] = bias[u0 + j];
    #pragma unroll
    for (int d = 0; d < 8; d++) { float a = nmA[d];
        #pragma unroll
        for (int j = 0; j < 8; j++) o[j] += a * W[d * ws + u0 + j]; }
    #pragma unroll
    for (int d = 0; d < 8; d++) { float a = nmB[d];
        #pragma unroll
        for (int j = 0; j < 8; j++) o[j] += a * W[(d + 8) * ws + u0 + j]; }
}
// silu + gamma/beta + rotary (chunk-aligned); gb: [0..127]=gamma, [128..255]=beta
__device__ __forceinline__ void gbrot8(float* o, int u0, const float* __restrict__ gb, int pos) {
    #pragma unroll
    for (int jj = 0; jj < 8; jj++) o[jj] = silu_f(o[jj]);
    if (u0 < ROTD) {
        #pragma unroll
        for (int jj = 0; jj < 8; jj += 2) {
            int u = u0 + jj;
            float a = o[jj] * gb[u] + gb[128 + u];
            float b = o[jj+1] * gb[u+1] + gb[128 + u + 1];
            float c = g_rc[pos * 16 + (u >> 1)], s = g_rs[pos * 16 + (u >> 1)];
            o[jj] = a * c - b * s;
            o[jj+1] = b * c + a * s;
        }
    } else {
        #pragma unroll
        for (int jj = 0; jj < 8; jj++) { int u = u0 + jj; o[jj] = o[jj] * gb[u] + gb[128 + u]; }
    }
}

// ---------------- K0 / K0b ----------------
__global__ void k_embed(const int* __restrict__ kmer, const float* __restrict__ emb,
                        const float* __restrict__ ps) {
    int idx = blockIdx.x * blockDim.x + threadIdx.x;
    if (idx >= BN * DIM) return;
    int d = idx & 15;
    int tok = idx >> 4;
    int t = tok % N;
    int j = (d < 8) ? d : d - 8;
    float inv = (float)exp(-(double)j * POS_LC);
    float ang = (float)t * inv;
    float p = (d < 8) ? sinf(ang) : cosf(ang);
    g_x[idx] = emb[kmer[tok] * DIM + d] + p * ps[0];
}
__global__ void k_rot() {
    int idx = blockIdx.x * blockDim.x + threadIdx.x;
    if (idx >= N * 16) return;
    int t = idx >> 4, j = idx & 15;
    float inv = (float)exp(-(double)j * ROT_LC);
    float ang = (float)t * inv;
    g_rc[idx] = cosf(ang);
    g_rs[idx] = sinf(ang);
}

// ---------------- kA: fused norm+proj+quad attention (8x8 tiles, AS aliases KT) ----------------
#define OF_SN  0          // [257][17] -> 4369, pad 4372
#define OF_QS  4372       // [128][132]
#define OF_KT  21268      // [128][132]; AS aliases this region with stride 130
#define OF_VS  38164      // [128][34]
#define OF_WQK 42516      // 2048
#define OF_WV  44564      // 512
#define OF_GBQ 45076      // 256
#define OF_GBK 45332      // 256
#define OF_BQK 45588      // 128
#define OF_BV  45716      // 32
#define KA_SMEM ((45748 + 12) * 4)   // 183040 B

__global__ void __launch_bounds__(256, 1) kA(const float* __restrict__ ng,
        const float* __restrict__ Wh, const float* __restrict__ bh,
        const float* __restrict__ Wqk, const float* __restrict__ bqk,
        const float* __restrict__ gamma, const float* __restrict__ beta) {
    extern __shared__ float s[];
    float* SN = s + OF_SN;  float* QS = s + OF_QS;  float* KT = s + OF_KT;
    float* AS = s + OF_KT;  float* VS = s + OF_VS;  float* WQ = s + OF_WQK;
    float* WV = s + OF_WV;  float* GQ = s + OF_GBQ; float* GK = s + OF_GBK;
    float* BQ = s + OF_BQK; float* BV = s + OF_BV;
    int tid = threadIdx.x;
    int qh = blockIdx.x, g = blockIdx.y, b = blockIdx.z;
    int gstart = g * GSZ;
    const int bN = b * N;

    for (int i = tid; i < 2048; i += 256) WQ[i] = Wqk[i];
    for (int i = tid; i < 512; i += 256) WV[i] = Wh[(i >> 5) * 64 + (i & 31)];
    if (tid < 128) {
        GQ[tid] = gamma[tid];       GQ[128 + tid] = beta[tid];
        GK[tid] = gamma[256 + tid]; GK[128 + tid] = beta[256 + tid];
        BQ[tid] = bqk[tid];
    }
    if (tid < 32) BV[tid] = bh[tid];
    for (int i = tid; i < 257 * 4; i += 256) {
        int r = i >> 2, d4 = (i & 3) * 4;
        int p = gstart - 1 + r;
        float4 v = make_float4(0, 0, 0, 0);
        if (p >= 0 && p < N) v = *(const float4*)&g_x[(long)(bN + p) * 16 + d4];
        SN[r*17 + d4] = v.x; SN[r*17 + d4+1] = v.y; SN[r*17 + d4+2] = v.z; SN[r*17 + d4+3] = v.w;
    }
    __syncthreads();
    float gng = ng[0];
    for (int i = tid; i < 257; i += 256) {
        float ss = 0;
        #pragma unroll
        for (int d = 0; d < 16; d++) { float v = SN[i*17 + d]; ss += v * v; }
        float scl = gng / fmaxf(sqrtf(ss) * 0.25f, 1e-5f);
        #pragma unroll
        for (int d = 0; d < 16; d++) SN[i*17 + d] *= scl;
    }
    __syncthreads();

    {   // Q tile (128 q tokens x 128 dims)
        int j = tid >> 1, h = tid & 1;
        int p = gstart + qh * 128 + j;
        int si = qh * 128 + j + 1;
        float nmA[8], nmB[8];
        bool first = (p == 0);
        #pragma unroll
        for (int d = 0; d < 8; d++) {
            nmA[d] = first ? 0.0f : SN[(si - 1) * 17 + d];
            nmB[d] = SN[si * 17 + 8 + d];
        }
        int rp = (p < N) ? p : 0;
        #pragma unroll
        for (int c = 0; c < 8; c++) {
            int u0 = h * 64 + c * 8;
            float o[8];
            proj8(nmA, nmB, WQ, 128, BQ, u0, o);
            gbrot8(o, u0, GQ, rp);
            #pragma unroll
            for (int jj = 0; jj < 8; jj += 2)
                *(float2*)&QS[j * 132 + u0 + jj] = make_float2(o[jj], o[jj+1]);
        }
    }

    ull oacc[8];
    #pragma unroll
    for (int e = 0; e < 8; e++) oacc[e] = 0ull;
    int oi = tid >> 1, eg = (tid & 1) * 16;
    int tx = tid & 15, ty = tid >> 4;

    for (int ck = 0; ck < 2; ck++) {
        __syncthreads();
        {   // build K chunk (transposed, 128 keys) + V chunk, proj recompute
            int t = tid & 127, q4 = tid >> 7;
            int kloc = ck * 128 + t;
            int p = gstart + kloc;
            int si = kloc + 1;
            float nmA[8], nmB[8];
            bool first = (p == 0);
            #pragma unroll
            for (int d = 0; d < 8; d++) {
                nmA[d] = first ? 0.0f : SN[(si - 1) * 17 + d];
                nmB[d] = SN[si * 17 + 8 + d];
            }
            int rp = (p < N) ? p : 0;
            #pragma unroll
            for (int cc = 0; cc < 8; cc++) {
                int u0 = q4 * 64 + cc * 8;
                float o[8];
                proj8(nmA, nmB, WQ, 128, BQ, u0, o);
                gbrot8(o, u0, GK, rp);
                #pragma unroll
                for (int jj = 0; jj < 8; jj++) KT[(u0 + jj) * 132 + t] = o[jj];
            }
            {   int e0 = q4 * 16;
                float o[8];
                proj8(nmA, nmB, WV, 32, BV, e0, o);
                #pragma unroll
                for (int jj = 0; jj < 8; jj++) VS[t * 34 + e0 + jj] = silu_f(o[jj]);
                proj8(nmA, nmB, WV, 32, BV, e0 + 8, o);
                #pragma unroll
                for (int jj = 0; jj < 8; jj++) VS[t * 34 + e0 + 8 + jj] = silu_f(o[jj]);
            }
        }
        __syncthreads();
        // stage A: sim rows {8ty+rr} x cols {2tx+32c,+1}, 8x8 per thread
        ull acc[8][4];
        #pragma unroll
        for (int r = 0; r < 8; r++)
            #pragma unroll
            for (int c = 0; c < 4; c++) acc[r][c] = 0ull;
        #pragma unroll 2
        for (int kk = 0; kk < 128; kk++) {
            ull kp[4];
            #pragma unroll
            for (int c = 0; c < 4; c++)
                kp[c] = *(const ull*)&KT[kk * 132 + 2 * tx + 32 * c];
            #pragma unroll
            for (int r = 0; r < 8; r++) {
                float qv = QS[(8 * ty + r) * 132 + kk];
                ull qd = pk2(qv, qv);
                #pragma unroll
                for (int c = 0; c < 4; c++) fma2(acc[r][c], qd, kp[c]);
            }
        }
        __syncthreads();   // all KT reads complete before alias overwrite
        {   int kb = gstart + ck * 128;
            #pragma unroll
            for (int r = 0; r < 8; r++) {
                int row = 8 * ty + r;
                #pragma unroll
                for (int c = 0; c < 4; c++) {
                    float2 f = up2(acc[r][c]);
                    int c0 = 2 * tx + 32 * c;
                    float s0 = fmaxf(f.x * (1.0f/256.0f), 0.0f); s0 *= s0;
                    float s1 = fmaxf(f.y * (1.0f/256.0f), 0.0f); s1 *= s1;
                    if (kb + c0     >= N) s0 = 0.0f;
                    if (kb + c0 + 1 >= N) s1 = 0.0f;
                    *(ull*)&AS[row * 130 + c0] = pk2(s0, s1);
                }
            }
        }
        __syncthreads();
        {   // stage B: O[oi][eg..eg+15] += A * V
            #pragma unroll 4
            for (int j = 0; j < 128; j++) {
                float a = AS[oi * 130 + j];
                ull ad = pk2(a, a);
                const ull* vp = (const ull*)&VS[j * 34 + eg];
                #pragma unroll
                for (int e = 0; e < 8; e++) fma2(oacc[e], ad, vp[e]);
            }
        }
    }
    int qp = gstart + qh * 128 + oi;
    if (qp < N) {
        float* dst = &g_qo[(long)(bN + qp) * 32 + eg];
        #pragma unroll
        for (int e = 0; e < 8; e++) { float2 f = up2(oacc[e]); *(float2*)&dst[e * 2] = f; }
    }
}

// ---------------- kB: fused lin-KV partials, 32-token chunks (grid: 8 x B) ----------------
__global__ void __launch_bounds__(256, 2) kB(const float* __restrict__ ng,
        const float* __restrict__ Wh, const float* __restrict__ bh,
        const float* __restrict__ Wqk, const float* __restrict__ bqk,
        const float* __restrict__ gamma, const float* __restrict__ beta) {
    __shared__ __align__(16) float SN[126 * 17];
    __shared__ __align__(16) float SLK[32][128];
    __shared__ __align__(16) float SV[32][32];
    __shared__ __align__(16) float WQ[2048];
    __shared__ __align__(16) float WV2[512];
    __shared__ __align__(16) float GB[256];
    __shared__ __align__(16) float BQ2[128];
    __shared__ __align__(16) float BV2[32];
    int tid = threadIdx.x;
    int sblk = blockIdx.x, b = blockIdx.y;
    const int bN = b * N;
    int p0 = sblk * 125;
    int cnt = min(125, N - p0);

    for (int i = tid; i < 2048; i += 256) WQ[i] = Wqk[i];
    for (int i = tid; i < 512; i += 256) WV2[i] = Wh[(i >> 5) * 64 + (i & 31)];
    if (tid < 128) {
        GB[tid] = gamma[3 * 128 + tid]; GB[128 + tid] = beta[3 * 128 + tid];
        BQ2[tid] = bqk[tid];
    }
    if (tid < 32) BV2[tid] = bh[tid];
    for (int i = tid; i < (cnt + 1) * 4; i += 256) {
        int r = i >> 2, d4 = (i & 3) * 4;
        int p = p0 - 1 + r;
        float4 v = make_float4(0, 0, 0, 0);
        if (p >= 0) v = *(const float4*)&g_x[(long)(bN + p) * 16 + d4];
        SN[r*17 + d4] = v.x; SN[r*17 + d4+1] = v.y; SN[r*17 + d4+2] = v.z; SN[r*17 + d4+3] = v.w;
    }
    __syncthreads();
    float gng = ng[0];
    for (int i = tid; i <= cnt; i += 256) {
        float ss = 0;
        #pragma unroll
        for (int d = 0; d < 16; d++) { float v = SN[i*17 + d]; ss += v * v; }
        float scl = gng / fmaxf(sqrtf(ss) * 0.25f, 1e-5f);
        #pragma unroll
        for (int d = 0; d < 16; d++) SN[i*17 + d] *= scl;
    }
    __syncthreads();

    ull acc[8];
    #pragma unroll
    for (int e = 0; e < 8; e++) acc[e] = 0ull;
    int dd = tid & 127, e0 = (tid >> 7) * 16;
    int r = tid >> 5, lane = tid & 31;

    for (int pp = 0; pp < cnt; pp += 32) {
        __syncthreads();
        #pragma unroll
        for (int s2 = 0; s2 < 4; s2++) {
            int trow = pp + r + 8 * s2;
            bool valid = trow < cnt;
            int p = p0 + trow;
            int sic = valid ? (trow + 1) : 1;
            bool first = (p == 0);
            float nmA[8], nmB[8];
            #pragma unroll
            for (int d = 0; d < 8; d++) {
                nmA[d] = (first || !valid) ? 0.0f : SN[(sic - 1) * 17 + d];
                nmB[d] = valid ? SN[sic * 17 + 8 + d] : 0.0f;
            }
            int rp = valid ? p : 0;
            #pragma unroll
            for (int j = 0; j < 4; j++) {
                int u = lane + 32 * j;
                float o = BQ2[u];
                #pragma unroll
                for (int d = 0; d < 8; d++) o += nmA[d] * WQ[d * 128 + u];
                #pragma unroll
                for (int d = 0; d < 8; d++) o += nmB[d] * WQ[(d + 8) * 128 + u];
                o = silu_f(o);
                o = o * GB[u] + GB[128 + u];
                if (j == 0) {
                    float c = g_rc[rp * 16 + (lane >> 1)], sn2 = g_rs[rp * 16 + (lane >> 1)];
                    float part = __shfl_xor_sync(0xffffffffu, o, 1);
                    o = (lane & 1) ? (o * c + part * sn2) : (o * c - part * sn2);
                }
                SLK[r + 8 * s2][u] = valid ? o : 0.0f;
            }
            {   float o = BV2[lane];
                #pragma unroll
                for (int d = 0; d < 8; d++) o += nmA[d] * WV2[d * 32 + lane];
                #pragma unroll
                for (int d = 0; d < 8; d++) o += nmB[d] * WV2[(d + 8) * 32 + lane];
                SV[r + 8 * s2][lane] = valid ? silu_f(o) : 0.0f;
            }
        }
        __syncthreads();
        #pragma unroll 8
        for (int rr = 0; rr < 32; rr++) {
            float lv = SLK[rr][dd];
            ull ld = pk2(lv, lv);
            const ulonglong2* vp = (const ulonglong2*)&SV[rr][e0];
            ulonglong2 va = vp[0], vb = vp[1], vc = vp[2], vd = vp[3];
            fma2(acc[0], ld, va.x); fma2(acc[1], ld, va.y);
            fma2(acc[2], ld, vb.x); fma2(acc[3], ld, vb.y);
            fma2(acc[4], ld, vc.x); fma2(acc[5], ld, vc.y);
            fma2(acc[6], ld, vd.x); fma2(acc[7], ld, vd.y);
        }
    }
    float* dst = &g_linkvp[((long)(b * 8 + sblk) * 128 + dd) * 32 + e0];
    #pragma unroll
    for (int e = 0; e < 8; e++) { float2 f = up2(acc[e]); *(float2*)&dst[e * 2] = f; }
}

// ---------------- kC: fused KV-reduce + lin_out + gate + Wo + residual ----------------
__global__ void __launch_bounds__(256, 2) kC(const float* __restrict__ ng,
        const float* __restrict__ Wh, const float* __restrict__ bh,
        const float* __restrict__ Wqk, const float* __restrict__ bqk,
        const float* __restrict__ gamma, const float* __restrict__ beta,
        const float* __restrict__ Wo, const float* __restrict__ bo) {
    __shared__ __align__(16) float SN[84 * 17];
    __shared__ __align__(16) float SKV[4096];
    __shared__ __align__(16) float WQ[2048];
    __shared__ __align__(16) float WG[512];
    __shared__ __align__(16) float GB[256];
    __shared__ __align__(16) float BQ2[128];
    __shared__ __align__(16) float BG[32];
    __shared__ __align__(16) float SWO[512];
    __shared__ __align__(16) float SBO[16];
    __shared__ __align__(16) float OVS[8][32];
    int tid = threadIdx.x;
    int ch = blockIdx.x, b = blockIdx.y;
    const int bN = b * N;
    int t0 = ch * 83;

    for (int i = tid; i < 2048; i += 256) WQ[i] = Wqk[i];
    for (int i = tid; i < 512; i += 256) {
        WG[i] = Wh[(i >> 5) * 64 + 32 + (i & 31)];
        SWO[i] = Wo[i];
    }
    if (tid < 128) {
        GB[tid] = gamma[128 + tid]; GB[128 + tid] = beta[128 + tid];
        BQ2[tid] = bqk[tid];
    }
    if (tid < 32) BG[tid] = bh[32 + tid];
    if (tid < 16) SBO[tid] = bo[tid];
    const float inv_n = 1.0f / (float)N;
    for (int i = tid; i < 1024; i += 256) {
        float4 ssum = make_float4(0, 0, 0, 0);
        #pragma unroll
        for (int k2 = 0; k2 < 8; k2++) {
            float4 p = ((const float4*)&g_linkvp[(long)(b * 8 + k2) * 4096])[i];
            ssum.x += p.x; ssum.y += p.y; ssum.z += p.z; ssum.w += p.w;
        }
        ((float4*)SKV)[i] = make_float4(ssum.x * inv_n, ssum.y * inv_n, ssum.z * inv_n, ssum.w * inv_n);
    }
    for (int i = tid; i < 84 * 4; i += 256) {
        int r = i >> 2, d4 = (i & 3) * 4;
        int p = t0 - 1 + r;
        float4 v = make_float4(0, 0, 0, 0);
        if (p >= 0 && p < N) v = *(const float4*)&g_x[(long)(bN + p) * 16 + d4];
        SN[r*17 + d4] = v.x; SN[r*17 + d4+1] = v.y; SN[r*17 + d4+2] = v.z; SN[r*17 + d4+3] = v.w;
    }
    __syncthreads();
    float gng = ng[0];
    for (int i = tid; i < 84; i += 256) {
        float ss = 0;
        #pragma unroll
        for (int d = 0; d < 16; d++) { float v = SN[i*17 + d]; ss += v * v; }
        float scl = gng / fmaxf(sqrtf(ss) * 0.25f, 1e-5f);
        #pragma unroll
        for (int d = 0; d < 16; d++) SN[i*17 + d] *= scl;
    }
    __syncthreads();

    int w = tid >> 5, lane = tid & 31;
    for (int tok = t0 + w; tok < t0 + 83; tok += 8) {
        int si = tok - t0 + 1;
        bool first = (tok == 0);
        float nmA[8], nmB[8];
        #pragma unroll
        for (int d = 0; d < 8; d++) {
            nmA[d] = first ? 0.0f : SN[(si - 1) * 17 + d];
            nmB[d] = SN[si * 17 + 8 + d];
        }
        float lq4[4];
        #pragma unroll
        for (int j = 0; j < 4; j++) {
            int u = lane + 32 * j;
            float o = BQ2[u];
            #pragma unroll
            for (int d = 0; d < 8; d++) o += nmA[d] * WQ[d * 128 + u];
            #pragma unroll
            for (int d = 0; d < 8; d++) o += nmB[d] * WQ[(d + 8) * 128 + u];
            o = silu_f(o);
            o = o * GB[u] + GB[128 + u];
            if (j == 0) {
                float c = g_rc[tok * 16 + (lane >> 1)], sn2 = g_rs[tok * 16 + (lane >> 1)];
                float part = __shfl_xor_sync(0xffffffffu, o, 1);
                o = (lane & 1) ? (o * c + part * sn2) : (o * c - part * sn2);
            }
            lq4[j] = o;
        }
        float gt;
        {   float o = BG[lane];
            #pragma unroll
            for (int d = 0; d < 8; d++) o += nmA[d] * WG[d * 32 + lane];
            #pragma unroll
            for (int d = 0; d < 8; d++) o += nmB[d] * WG[(d + 8) * 32 + lane];
            gt = silu_f(o);
        }
        float acc = g_qo[(long)(bN + tok) * 32 + lane];
        #pragma unroll
        for (int j = 0; j < 4; j++) {
            #pragma unroll
            for (int src = 0; src < 32; src++) {
                float lv = __shfl_sync(0xffffffffu, lq4[j], src);
                acc += lv * SKV[(src + 32 * j) * 32 + lane];
            }
        }
        acc *= gt;
        OVS[w][lane] = acc;
        __syncwarp();
        if (lane < 16) {
            float y = SBO[lane];
            #pragma unroll
            for (int e = 0; e < 32; e++) y += OVS[w][e] * SWO[e * 16 + lane];
            g_x[(long)(bN + tok) * 16 + lane] += y;
        }
        __syncwarp();
    }
}

// ---------------- k_logits / k_head ----------------
#define LOGITS_SMEM ((16*1024 + 1024 + 16*16) * 4)
__global__ void k_logits(const float* __restrict__ fg, const float* __restrict__ Wl,
                         const float* __restrict__ blv) {
    extern __shared__ float sm[];
    float* sW = sm;
    float* sb = sW + 16 * 1024;
    float* xn = sb + 1024;
    __shared__ float wred[8];
    __shared__ float xs[16];
    int tid = threadIdx.x;
    int base = blockIdx.x * 16;
    for (int i = tid; i < (16 * 1024) / 4; i += 256)
        ((float4*)sW)[i] = ((const float4*)Wl)[i];
    for (int i = tid; i < 1024; i += 256) sb[i] = blv[i];
    {   int tt = tid >> 4, d = tid & 15;
        xn[tt * 16 + d] = g_x[(long)(base + tt) * DIM + d];
    }
    __syncthreads();
    if (tid < 16) {
        float ss = 0;
        #pragma unroll
        for (int d = 0; d < 16; d++) { float v = xn[tid * 16 + d]; ss += v * v; }
        xs[tid] = fg[0] / fmaxf(sqrtf(ss) * 0.25f, 1e-5f);
    }
    __syncthreads();
    {   int tt = tid >> 4, d = tid & 15;
        xn[tt * 16 + d] *= xs[tt];
    }
    __syncthreads();
    int warp = tid >> 5, lane = tid & 31;
    int v0 = tid * 4;
    for (int tt = 0; tt < 16; tt++) {
        float s0 = sb[v0], s1 = sb[v0+1], s2 = sb[v0+2], s3 = sb[v0+3];
        #pragma unroll
        for (int d = 0; d < 16; d++) {
            float xv = xn[tt * 16 + d];
            float4 wv = *(const float4*)&sW[d * 1024 + v0];
            s0 += xv * wv.x; s1 += xv * wv.y; s2 += xv * wv.z; s3 += xv * wv.w;
        }
        float m = fmaxf(fmaxf(s0, s1), fmaxf(s2, s3));
        #pragma unroll
        for (int off = 16; off > 0; off >>= 1)
            m = fmaxf(m, __shfl_xor_sync(0xffffffff, m, off));
        if (lane == 0) wred[warp] = m;
        __syncthreads();
        if (tid == 0) {
            float mm = wred[0];
            #pragma unroll
            for (int j = 1; j < 8; j++) mm = fmaxf(mm, wred[j]);
            g_hmax[base + tt] = mm;
        }
        __syncthreads();
    }
}
__global__ void k_head(const float* __restrict__ W1, const float* __restrict__ b1,
                       const float* __restrict__ W2, const float* __restrict__ b2,
                       float* __restrict__ out) {
    __shared__ float red[8][32];
    __shared__ float rr[32];
    int tid = threadIdx.x;
    int b = blockIdx.x;
    int col = tid & 31, seg = tid >> 5;
    float acc = 0.0f;
    int t0 = seg * 125;
    int t1 = min(t0 + 125, N);
    for (int t = t0; t < t1; t++)
        acc += g_hmax[(long)b * N + t] * W1[t * 32 + col];
    red[seg][col] = acc;
    __syncthreads();
    if (tid < 32) {
        float ss = b1[tid];
        #pragma unroll
        for (int k = 0; k < 8; k++) ss += red[k][tid];
        rr[tid] = fmaxf(ss, 0.0f);
    }
    __syncthreads();
    if (tid == 0) {
        float o = b2[0];
        #pragma unroll
        for (int j = 0; j < 32; j++) o += rr[j] * W2[j];
        out[b] = o;
    }
}

// ---------------- launch ----------------
extern "C" void kernel_launch(void* const* d_in, const int* in_sizes, int n_in,
                              void* d_out, int out_size) {
    const int*   kmer    = (const int*)  d_in[0];
    const float* emb     = (const float*)d_in[1];
    const float* psc     = (const float*)d_in[2];
    const float* norm_g  = (const float*)d_in[3];
    const float* Wh      = (const float*)d_in[4];
    const float* bh      = (const float*)d_in[5];
    const float* Wqk     = (const float*)d_in[6];
    const float* bqk     = (const float*)d_in[7];
    const float* gamma   = (const float*)d_in[8];
    const float* beta    = (const float*)d_in[9];
    const float* Wo      = (const float*)d_in[10];
    const float* bo      = (const float*)d_in[11];
    const float* fg      = (const float*)d_in[12];
    const float* Wl      = (const float*)d_in[13];
    const float* bl      = (const float*)d_in[14];
    const float* W1      = (const float*)d_in[15];
    const float* b1      = (const float*)d_in[16];
    const float* W2      = (const float*)d_in[17];
    const float* b2      = (const float*)d_in[18];
    float* out = (float*)d_out;

    cudaFuncSetAttribute(kA, cudaFuncAttributeMaxDynamicSharedMemorySize, KA_SMEM);
    cudaFuncSetAttribute(k_logits, cudaFuncAttributeMaxDynamicSharedMemorySize, LOGITS_SMEM);

    k_embed<<<(BN * DIM + 255) / 256, 256>>>(kmer, emb, psc);
    k_rot<<<(N * 16 + 255) / 256, 256>>>();

    for (int l = 0; l < DEPTH; l++) {
        const float* Whl = Wh + (long)l * 16 * 64;
        const float* bhl = bh + (long)l * 64;
        const float* Wql = Wqk + (long)l * 16 * 128;
        const float* bql = bqk + (long)l * 128;
        const float* gml = gamma + (long)l * 4 * 128;
        const float* btl = beta + (long)l * 4 * 128;
        kA<<<dim3(2, NG, B), 256, KA_SMEM>>>(norm_g + l, Whl, bhl, Wql, bql, gml, btl);
        kB<<<dim3(8, B), 256>>>(norm_g + l, Whl, bhl, Wql, bql, gml, btl);
        kC<<<dim3(12, B), 256>>>(norm_g + l, Whl, bhl, Wql, bql, gml, btl,
                                 Wo + (long)l * 32 * DIM, bo + (long)l * DIM);
    }

    k_logits<<<BN / 16, 256, LOGITS_SMEM>>>(fg, Wl, bl);
    k_head<<<B, 256>>>(W1, b1, W2, b2, out);
    (void)in_sizes; (void)n_in; (void)out_size;
}

// round 10
// speedup vs baseline: 1.5644x; 1.5644x over previous
#include <cuda_runtime.h>
#include <math.h>

#define B 128
#define N 996
#define BN (B*N)
#define DIM 16
#define QKD 128
#define GSZ 256
#define NG 4
#define DEPTH 8
#define VOC 1024
#define ROTD 32

// ---------------- scratch ----------------
__device__ __align__(16) float g_x[BN*DIM];
__device__ __align__(16) float g_qo[BN*32];          // ungated quad attention out
__device__ __align__(16) float g_linkvp[B*8*128*32];
__device__ float g_rc[N*16];
__device__ float g_rs[N*16];
__device__ float g_hmax[BN];

#define ROT_LC 0.57564627324851142
#define POS_LC 1.1512925464970228

typedef unsigned long long ull;

__device__ __forceinline__ ull pk2(float a, float b) {
    ull r; asm("mov.b64 %0,{%1,%2};" : "=l"(r) : "f"(a), "f"(b)); return r;
}
__device__ __forceinline__ void fma2(ull& d, ull a, ull b) {
    asm("fma.rn.f32x2 %0,%1,%2,%0;" : "+l"(d) : "l"(a), "l"(b));
}
__device__ __forceinline__ float2 up2(ull v) {
    float2 f; asm("mov.b64 {%0,%1},%2;" : "=f"(f.x), "=f"(f.y) : "l"(v)); return f;
}
__device__ __forceinline__ float silu_f(float a) {
    return __fdividef(a, 1.0f + __expf(-a));
}

// proj 8 outputs [u0,u0+8) ; nmA = prev-token normed d0..7, nmB = cur normed d8..15
__device__ __forceinline__ void proj8(const float* nmA, const float* nmB,
                                      const float* __restrict__ W, int ws,
                                      const float* __restrict__ bias, int u0, float* o) {
    #pragma unroll
    for (int j = 0; j < 8; j++) o[j] = bias[u0 + j];
    #pragma unroll
    for (int d = 0; d < 8; d++) { float a = nmA[d];
        #pragma unroll
        for (int j = 0; j < 8; j++) o[j] += a * W[d * ws + u0 + j]; }
    #pragma unroll
    for (int d = 0; d < 8; d++) { float a = nmB[d];
        #pragma unroll
        for (int j = 0; j < 8; j++) o[j] += a * W[(d + 8) * ws + u0 + j]; }
}
// silu + gamma/beta + rotary (chunk-aligned); gb: [0..127]=gamma, [128..255]=beta
__device__ __forceinline__ void gbrot8(float* o, int u0, const float* __restrict__ gb, int pos) {
    #pragma unroll
    for (int jj = 0; jj < 8; jj++) o[jj] = silu_f(o[jj]);
    if (u0 < ROTD) {
        #pragma unroll
        for (int jj = 0; jj < 8; jj += 2) {
            int u = u0 + jj;
            float a = o[jj] * gb[u] + gb[128 + u];
            float b = o[jj+1] * gb[u+1] + gb[128 + u + 1];
            float c = g_rc[pos * 16 + (u >> 1)], s = g_rs[pos * 16 + (u >> 1)];
            o[jj] = a * c - b * s;
            o[jj+1] = b * c + a * s;
        }
    } else {
        #pragma unroll
        for (int jj = 0; jj < 8; jj++) { int u = u0 + jj; o[jj] = o[jj] * gb[u] + gb[128 + u]; }
    }
}

// ---------------- K0 / K0b ----------------
__global__ void k_embed(const int* __restrict__ kmer, const float* __restrict__ emb,
                        const float* __restrict__ ps) {
    int idx = blockIdx.x * blockDim.x + threadIdx.x;
    if (idx >= BN * DIM) return;
    int d = idx & 15;
    int tok = idx >> 4;
    int t = tok % N;
    int j = (d < 8) ? d : d - 8;
    float inv = (float)exp(-(double)j * POS_LC);
    float ang = (float)t * inv;
    float p = (d < 8) ? sinf(ang) : cosf(ang);
    g_x[idx] = emb[kmer[tok] * DIM + d] + p * ps[0];
}
__global__ void k_rot() {
    int idx = blockIdx.x * blockDim.x + threadIdx.x;
    if (idx >= N * 16) return;
    int t = idx >> 4, j = idx & 15;
    float inv = (float)exp(-(double)j * ROT_LC);
    float ang = (float)t * inv;
    g_rc[idx] = cosf(ang);
    g_rs[idx] = sinf(ang);
}

// ---------------- kA: fused norm+proj+quad attention ----------------
// dyn smem (floats):
#define OF_SN  0          // [257][17]
#define OF_QS  4372       // [128][132]
#define OF_KT  21268      // [128][66]  transposed K chunk
#define OF_AS  29716      // [128][66]
#define OF_VS  38164      // [64][34]
#define OF_WQK 40340      // [16][128]
#define OF_WV  42388      // [16][32]
#define OF_GBQ 42900      // gamma|beta quad_q
#define OF_GBK 43156      // gamma|beta quad_k
#define OF_BQK 43412
#define OF_BV  43540
#define KA_SMEM ((43540 + 32) * 4)   // 174288 B

__global__ void __launch_bounds__(256, 1) kA(const float* __restrict__ ng,
        const float* __restrict__ Wh, const float* __restrict__ bh,
        const float* __restrict__ Wqk, const float* __restrict__ bqk,
        const float* __restrict__ gamma, const float* __restrict__ beta) {
    extern __shared__ float s[];
    float* SN = s + OF_SN;  float* QS = s + OF_QS;  float* KT = s + OF_KT;
    float* AS = s + OF_AS;  float* VS = s + OF_VS;  float* WQ = s + OF_WQK;
    float* WV = s + OF_WV;  float* GQ = s + OF_GBQ; float* GK = s + OF_GBK;
    float* BQ = s + OF_BQK; float* BV = s + OF_BV;
    int tid = threadIdx.x;
    int qh = blockIdx.x, g = blockIdx.y, b = blockIdx.z;
    int gstart = g * GSZ;
    const int bN = b * N;

    for (int i = tid; i < 2048; i += 256) WQ[i] = Wqk[i];
    for (int i = tid; i < 512; i += 256) WV[i] = Wh[(i >> 5) * 64 + (i & 31)];
    if (tid < 128) {
        GQ[tid] = gamma[tid];       GQ[128 + tid] = beta[tid];
        GK[tid] = gamma[256 + tid]; GK[128 + tid] = beta[256 + tid];
        BQ[tid] = bqk[tid];
    }
    if (tid < 32) BV[tid] = bh[tid];
    for (int i = tid; i < 257 * 4; i += 256) {
        int r = i >> 2, d4 = (i & 3) * 4;
        int p = gstart - 1 + r;
        float4 v = make_float4(0, 0, 0, 0);
        if (p >= 0 && p < N) v = *(const float4*)&g_x[(long)(bN + p) * 16 + d4];
        SN[r*17 + d4] = v.x; SN[r*17 + d4+1] = v.y; SN[r*17 + d4+2] = v.z; SN[r*17 + d4+3] = v.w;
    }
    __syncthreads();
    float gng = ng[0];
    for (int i = tid; i < 257; i += 256) {
        float ss = 0;
        #pragma unroll
        for (int d = 0; d < 16; d++) { float v = SN[i*17 + d]; ss += v * v; }
        float scl = gng / fmaxf(sqrtf(ss) * 0.25f, 1e-5f);
        #pragma unroll
        for (int d = 0; d < 16; d++) SN[i*17 + d] *= scl;
    }
    __syncthreads();

    {   // phase1: Q tile (128 q tokens x 128 dims)
        int j = tid >> 1, h = tid & 1;
        int p = gstart + qh * 128 + j;
        int si = qh * 128 + j + 1;
        float nmA[8], nmB[8];
        bool first = (p == 0);
        #pragma unroll
        for (int d = 0; d < 8; d++) {
            nmA[d] = first ? 0.0f : SN[(si - 1) * 17 + d];
            nmB[d] = SN[si * 17 + 8 + d];
        }
        int rp = (p < N) ? p : 0;
        #pragma unroll
        for (int c = 0; c < 8; c++) {
            int u0 = h * 64 + c * 8;
            float o[8];
            proj8(nmA, nmB, WQ, 128, BQ, u0, o);
            gbrot8(o, u0, GQ, rp);
            #pragma unroll
            for (int jj = 0; jj < 8; jj += 2)
                *(float2*)&QS[j * 132 + u0 + jj] = make_float2(o[jj], o[jj+1]);
        }
    }

    ull oacc[8];
    #pragma unroll
    for (int e = 0; e < 8; e++) oacc[e] = 0ull;
    int oi = tid >> 1, eg = (tid & 1) * 16;
    int tx = tid & 7, ty = tid >> 3;

    for (int ck = 0; ck < 4; ck++) {
        __syncthreads();
        {   // build K chunk (transposed) + V chunk, 64 keys, with proj recompute
            int t = tid & 63, q4 = tid >> 6;
            int kloc = ck * 64 + t;
            int p = gstart + kloc;
            int si = kloc + 1;
            float nmA[8], nmB[8];
            bool first = (p == 0);
            #pragma unroll
            for (int d = 0; d < 8; d++) {
                nmA[d] = first ? 0.0f : SN[(si - 1) * 17 + d];
                nmB[d] = SN[si * 17 + 8 + d];
            }
            int rp = (p < N) ? p : 0;
            #pragma unroll
            for (int cc = 0; cc < 4; cc++) {
                int u0 = q4 * 32 + cc * 8;
                float o[8];
                proj8(nmA, nmB, WQ, 128, BQ, u0, o);
                gbrot8(o, u0, GK, rp);
                #pragma unroll
                for (int jj = 0; jj < 8; jj++) KT[(u0 + jj) * 66 + t] = o[jj];
            }
            {   int e0 = q4 * 8;
                float o[8];
                proj8(nmA, nmB, WV, 32, BV, e0, o);
                #pragma unroll
                for (int jj = 0; jj < 8; jj++) VS[t * 34 + e0 + jj] = silu_f(o[jj]);
            }
        }
        __syncthreads();
        {   // stage A: sim rows (4ty+r) x cols (2tx+16c)
            ull acc[4][4];
            #pragma unroll
            for (int r = 0; r < 4; r++)
                #pragma unroll
                for (int c = 0; c < 4; c++) acc[r][c] = 0ull;
            #pragma unroll 4
            for (int kk = 0; kk < 128; kk++) {
                ull kp[4];
                #pragma unroll
                for (int c = 0; c < 4; c++)
                    kp[c] = *(const ull*)&KT[kk * 66 + 2 * tx + 16 * c];
                #pragma unroll
                for (int r = 0; r < 4; r++) {
                    float qv = QS[(4 * ty + r) * 132 + kk];
                    ull qd = pk2(qv, qv);
                    #pragma unroll
                    for (int c = 0; c < 4; c++) fma2(acc[r][c], qd, kp[c]);
                }
            }
            int kb = gstart + ck * 64;
            #pragma unroll
            for (int r = 0; r < 4; r++) {
                int row = 4 * ty + r;
                #pragma unroll
                for (int c = 0; c < 4; c++) {
                    float2 f = up2(acc[r][c]);
                    int c0 = 2 * tx + 16 * c;
                    float s0 = fmaxf(f.x * (1.0f/256.0f), 0.0f); s0 *= s0;
                    float s1 = fmaxf(f.y * (1.0f/256.0f), 0.0f); s1 *= s1;
                    if (kb + c0     >= N) s0 = 0.0f;
                    if (kb + c0 + 1 >= N) s1 = 0.0f;
                    *(ull*)&AS[row * 66 + c0] = pk2(s0, s1);
                }
            }
        }
        __syncthreads();
        {   // stage B: O[oi][eg..eg+15] += A * V
            #pragma unroll 4
            for (int j = 0; j < 64; j++) {
                float a = AS[oi * 66 + j];
                ull ad = pk2(a, a);
                const ull* vp = (const ull*)&VS[j * 34 + eg];
                #pragma unroll
                for (int e = 0; e < 8; e++) fma2(oacc[e], ad, vp[e]);
            }
        }
    }
    int qp = gstart + qh * 128 + oi;
    if (qp < N) {
        float* dst = &g_qo[(long)(bN + qp) * 32 + eg];
        #pragma unroll
        for (int e = 0; e < 8; e++) { float2 f = up2(oacc[e]); *(float2*)&dst[e * 2] = f; }
    }
}

// ---------------- kB: fused lin-KV partials (grid: 8 x B) ----------------
__global__ void __launch_bounds__(256, 2) kB(const float* __restrict__ ng,
        const float* __restrict__ Wh, const float* __restrict__ bh,
        const float* __restrict__ Wqk, const float* __restrict__ bqk,
        const float* __restrict__ gamma, const float* __restrict__ beta) {
    __shared__ __align__(16) float SN[126 * 17];
    __shared__ __align__(16) float SLK[8][128];
    __shared__ __align__(16) float SV[8][32];
    __shared__ __align__(16) float WQ[2048];
    __shared__ __align__(16) float WV2[512];
    __shared__ __align__(16) float GB[256];
    __shared__ __align__(16) float BQ2[128];
    __shared__ __align__(16) float BV2[32];
    int tid = threadIdx.x;
    int sblk = blockIdx.x, b = blockIdx.y;
    const int bN = b * N;
    int p0 = sblk * 125;
    int cnt = min(125, N - p0);

    for (int i = tid; i < 2048; i += 256) WQ[i] = Wqk[i];
    for (int i = tid; i < 512; i += 256) WV2[i] = Wh[(i >> 5) * 64 + (i & 31)];
    if (tid < 128) {
        GB[tid] = gamma[3 * 128 + tid]; GB[128 + tid] = beta[3 * 128 + tid];
        BQ2[tid] = bqk[tid];
    }
    if (tid < 32) BV2[tid] = bh[tid];
    for (int i = tid; i < (cnt + 1) * 4; i += 256) {
        int r = i >> 2, d4 = (i & 3) * 4;
        int p = p0 - 1 + r;
        float4 v = make_float4(0, 0, 0, 0);
        if (p >= 0) v = *(const float4*)&g_x[(long)(bN + p) * 16 + d4];
        SN[r*17 + d4] = v.x; SN[r*17 + d4+1] = v.y; SN[r*17 + d4+2] = v.z; SN[r*17 + d4+3] = v.w;
    }
    __syncthreads();
    float gng = ng[0];
    for (int i = tid; i <= cnt; i += 256) {
        float ss = 0;
        #pragma unroll
        for (int d = 0; d < 16; d++) { float v = SN[i*17 + d]; ss += v * v; }
        float scl = gng / fmaxf(sqrtf(ss) * 0.25f, 1e-5f);
        #pragma unroll
        for (int d = 0; d < 16; d++) SN[i*17 + d] *= scl;
    }
    __syncthreads();

    ull acc[8];
    #pragma unroll
    for (int e = 0; e < 8; e++) acc[e] = 0ull;
    int dd = tid & 127, e0 = (tid >> 7) * 16;
    int r = tid >> 5, lane = tid & 31;

    for (int pp = 0; pp < cnt; pp += 8) {
        __syncthreads();
        {   int p = p0 + pp + r;
            bool valid = (pp + r) < cnt;
            int sic = valid ? (pp + r + 1) : 1;
            bool first = (p == 0);
            float nmA[8], nmB[8];
            #pragma unroll
            for (int d = 0; d < 8; d++) {
                nmA[d] = (first || !valid) ? 0.0f : SN[(sic - 1) * 17 + d];
                nmB[d] = valid ? SN[sic * 17 + 8 + d] : 0.0f;
            }
            int rp = valid ? p : 0;
            #pragma unroll
            for (int j = 0; j < 4; j++) {
                int u = lane + 32 * j;
                float o = BQ2[u];
                #pragma unroll
                for (int d = 0; d < 8; d++) o += nmA[d] * WQ[d * 128 + u];
                #pragma unroll
                for (int d = 0; d < 8; d++) o += nmB[d] * WQ[(d + 8) * 128 + u];
                o = silu_f(o);
                o = o * GB[u] + GB[128 + u];
                if (j == 0) {
                    float c = g_rc[rp * 16 + (lane >> 1)], sn2 = g_rs[rp * 16 + (lane >> 1)];
                    float part = __shfl_xor_sync(0xffffffffu, o, 1);
                    o = (lane & 1) ? (o * c + part * sn2) : (o * c - part * sn2);
                }
                SLK[r][u] = valid ? o : 0.0f;
            }
            {   float o = BV2[lane];
                #pragma unroll
                for (int d = 0; d < 8; d++) o += nmA[d] * WV2[d * 32 + lane];
                #pragma unroll
                for (int d = 0; d < 8; d++) o += nmB[d] * WV2[(d + 8) * 32 + lane];
                SV[r][lane] = valid ? silu_f(o) : 0.0f;
            }
        }
        __syncthreads();
        #pragma unroll
        for (int rr = 0; rr < 8; rr++) {
            float lv = SLK[rr][dd];
            ull ld = pk2(lv, lv);
            const ulonglong2* vp = (const ulonglong2*)&SV[rr][e0];
            ulonglong2 va = vp[0], vb = vp[1], vc = vp[2], vd = vp[3];
            fma2(acc[0], ld, va.x); fma2(acc[1], ld, va.y);
            fma2(acc[2], ld, vb.x); fma2(acc[3], ld, vb.y);
            fma2(acc[4], ld, vc.x); fma2(acc[5], ld, vc.y);
            fma2(acc[6], ld, vd.x); fma2(acc[7], ld, vd.y);
        }
    }
    float* dst = &g_linkvp[((long)(b * 8 + sblk) * 128 + dd) * 32 + e0];
    #pragma unroll
    for (int e = 0; e < 8; e++) { float2 f = up2(acc[e]); *(float2*)&dst[e * 2] = f; }
}

// ---------------- kC: fused KV-reduce + lin_out + gate + Wo + residual ----------------
__global__ void __launch_bounds__(256, 2) kC(const float* __restrict__ ng,
        const float* __restrict__ Wh, const float* __restrict__ bh,
        const float* __restrict__ Wqk, const float* __restrict__ bqk,
        const float* __restrict__ gamma, const float* __restrict__ beta,
        const float* __restrict__ Wo, const float* __restrict__ bo) {
    __shared__ __align__(16) float SN[84 * 17];
    __shared__ __align__(16) float SKV[4096];
    __shared__ __align__(16) float WQ[2048];
    __shared__ __align__(16) float WG[512];
    __shared__ __align__(16) float GB[256];
    __shared__ __align__(16) float BQ2[128];
    __shared__ __align__(16) float BG[32];
    __shared__ __align__(16) float SWO[512];
    __shared__ __align__(16) float SBO[16];
    __shared__ __align__(16) float OVS[8][32];
    int tid = threadIdx.x;
    int ch = blockIdx.x, b = blockIdx.y;
    const int bN = b * N;
    int t0 = ch * 83;

    for (int i = tid; i < 2048; i += 256) WQ[i] = Wqk[i];
    for (int i = tid; i < 512; i += 256) {
        WG[i] = Wh[(i >> 5) * 64 + 32 + (i & 31)];
        SWO[i] = Wo[i];
    }
    if (tid < 128) {
        GB[tid] = gamma[128 + tid]; GB[128 + tid] = beta[128 + tid];
        BQ2[tid] = bqk[tid];
    }
    if (tid < 32) BG[tid] = bh[32 + tid];
    if (tid < 16) SBO[tid] = bo[tid];
    const float inv_n = 1.0f / (float)N;
    for (int i = tid; i < 1024; i += 256) {
        float4 ssum = make_float4(0, 0, 0, 0);
        #pragma unroll
        for (int k2 = 0; k2 < 8; k2++) {
            float4 p = ((const float4*)&g_linkvp[(long)(b * 8 + k2) * 4096])[i];
            ssum.x += p.x; ssum.y += p.y; ssum.z += p.z; ssum.w += p.w;
        }
        ((float4*)SKV)[i] = make_float4(ssum.x * inv_n, ssum.y * inv_n, ssum.z * inv_n, ssum.w * inv_n);
    }
    for (int i = tid; i < 84 * 4; i += 256) {
        int r = i >> 2, d4 = (i & 3) * 4;
        int p = t0 - 1 + r;
        float4 v = make_float4(0, 0, 0, 0);
        if (p >= 0 && p < N) v = *(const float4*)&g_x[(long)(bN + p) * 16 + d4];
        SN[r*17 + d4] = v.x; SN[r*17 + d4+1] = v.y; SN[r*17 + d4+2] = v.z; SN[r*17 + d4+3] = v.w;
    }
    __syncthreads();
    float gng = ng[0];
    for (int i = tid; i < 84; i += 256) {
        float ss = 0;
        #pragma unroll
        for (int d = 0; d < 16; d++) { float v = SN[i*17 + d]; ss += v * v; }
        float scl = gng / fmaxf(sqrtf(ss) * 0.25f, 1e-5f);
        #pragma unroll
        for (int d = 0; d < 16; d++) SN[i*17 + d] *= scl;
    }
    __syncthreads();

    int w = tid >> 5, lane = tid & 31;
    for (int tok = t0 + w; tok < t0 + 83; tok += 8) {
        int si = tok - t0 + 1;
        bool first = (tok == 0);
        float nmA[8], nmB[8];
        #pragma unroll
        for (int d = 0; d < 8; d++) {
            nmA[d] = first ? 0.0f : SN[(si - 1) * 17 + d];
            nmB[d] = SN[si * 17 + 8 + d];
        }
        float lq4[4];
        #pragma unroll
        for (int j = 0; j < 4; j++) {
            int u = lane + 32 * j;
            float o = BQ2[u];
            #pragma unroll
            for (int d = 0; d < 8; d++) o += nmA[d] * WQ[d * 128 + u];
            #pragma unroll
            for (int d = 0; d < 8; d++) o += nmB[d] * WQ[(d + 8) * 128 + u];
            o = silu_f(o);
            o = o * GB[u] + GB[128 + u];
            if (j == 0) {
                float c = g_rc[tok * 16 + (lane >> 1)], sn2 = g_rs[tok * 16 + (lane >> 1)];
                float part = __shfl_xor_sync(0xffffffffu, o, 1);
                o = (lane & 1) ? (o * c + part * sn2) : (o * c - part * sn2);
            }
            lq4[j] = o;
        }
        float gt;
        {   float o = BG[lane];
            #pragma unroll
            for (int d = 0; d < 8; d++) o += nmA[d] * WG[d * 32 + lane];
            #pragma unroll
            for (int d = 0; d < 8; d++) o += nmB[d] * WG[(d + 8) * 32 + lane];
            gt = silu_f(o);
        }
        float acc = g_qo[(long)(bN + tok) * 32 + lane];
        #pragma unroll
        for (int j = 0; j < 4; j++) {
            #pragma unroll
            for (int src = 0; src < 32; src++) {
                float lv = __shfl_sync(0xffffffffu, lq4[j], src);
                acc += lv * SKV[(src + 32 * j) * 32 + lane];
            }
        }
        acc *= gt;
        OVS[w][lane] = acc;
        __syncwarp();
        if (lane < 16) {
            float y = SBO[lane];
            #pragma unroll
            for (int e = 0; e < 32; e++) y += OVS[w][e] * SWO[e * 16 + lane];
            g_x[(long)(bN + tok) * 16 + lane] += y;
        }
        __syncwarp();
    }
}

// ---------------- k_logits / k_head ----------------
#define LOGITS_SMEM ((16*1024 + 1024 + 16*16) * 4)
__global__ void k_logits(const float* __restrict__ fg, const float* __restrict__ Wl,
                         const float* __restrict__ blv) {
    extern __shared__ float sm[];
    float* sW = sm;
    float* sb = sW + 16 * 1024;
    float* xn = sb + 1024;
    __shared__ float wred[8];
    __shared__ float xs[16];
    int tid = threadIdx.x;
    int base = blockIdx.x * 16;
    for (int i = tid; i < (16 * 1024) / 4; i += 256)
        ((float4*)sW)[i] = ((const float4*)Wl)[i];
    for (int i = tid; i < 1024; i += 256) sb[i] = blv[i];
    {   int tt = tid >> 4, d = tid & 15;
        xn[tt * 16 + d] = g_x[(long)(base + tt) * DIM + d];
    }
    __syncthreads();
    if (tid < 16) {
        float ss = 0;
        #pragma unroll
        for (int d = 0; d < 16; d++) { float v = xn[tid * 16 + d]; ss += v * v; }
        xs[tid] = fg[0] / fmaxf(sqrtf(ss) * 0.25f, 1e-5f);
    }
    __syncthreads();
    {   int tt = tid >> 4, d = tid & 15;
        xn[tt * 16 + d] *= xs[tt];
    }
    __syncthreads();
    int warp = tid >> 5, lane = tid & 31;
    int v0 = tid * 4;
    for (int tt = 0; tt < 16; tt++) {
        float s0 = sb[v0], s1 = sb[v0+1], s2 = sb[v0+2], s3 = sb[v0+3];
        #pragma unroll
        for (int d = 0; d < 16; d++) {
            float xv = xn[tt * 16 + d];
            float4 wv = *(const float4*)&sW[d * 1024 + v0];
            s0 += xv * wv.x; s1 += xv * wv.y; s2 += xv * wv.z; s3 += xv * wv.w;
        }
        float m = fmaxf(fmaxf(s0, s1), fmaxf(s2, s3));
        #pragma unroll
        for (int off = 16; off > 0; off >>= 1)
            m = fmaxf(m, __shfl_xor_sync(0xffffffff, m, off));
        if (lane == 0) wred[warp] = m;
        __syncthreads();
        if (tid == 0) {
            float mm = wred[0];
            #pragma unroll
            for (int j = 1; j < 8; j++) mm = fmaxf(mm, wred[j]);
            g_hmax[base + tt] = mm;
        }
        __syncthreads();
    }
}
__global__ void k_head(const float* __restrict__ W1, const float* __restrict__ b1,
                       const float* __restrict__ W2, const float* __restrict__ b2,
                       float* __restrict__ out) {
    __shared__ float red[8][32];
    __shared__ float rr[32];
    int tid = threadIdx.x;
    int b = blockIdx.x;
    int col = tid & 31, seg = tid >> 5;
    float acc = 0.0f;
    int t0 = seg * 125;
    int t1 = min(t0 + 125, N);
    for (int t = t0; t < t1; t++)
        acc += g_hmax[(long)b * N + t] * W1[t * 32 + col];
    red[seg][col] = acc;
    __syncthreads();
    if (tid < 32) {
        float ss = b1[tid];
        #pragma unroll
        for (int k = 0; k < 8; k++) ss += red[k][tid];
        rr[tid] = fmaxf(ss, 0.0f);
    }
    __syncthreads();
    if (tid == 0) {
        float o = b2[0];
        #pragma unroll
        for (int j = 0; j < 32; j++) o += rr[j] * W2[j];
        out[b] = o;
    }
}

// ---------------- launch ----------------
extern "C" void kernel_launch(void* const* d_in, const int* in_sizes, int n_in,
                              void* d_out, int out_size) {
    const int*   kmer    = (const int*)  d_in[0];
    const float* emb     = (const float*)d_in[1];
    const float* psc     = (const float*)d_in[2];
    const float* norm_g  = (const float*)d_in[3];
    const float* Wh      = (const float*)d_in[4];
    const float* bh      = (const float*)d_in[5];
    const float* Wqk     = (const float*)d_in[6];
    const float* bqk     = (const float*)d_in[7];
    const float* gamma   = (const float*)d_in[8];
    const float* beta    = (const float*)d_in[9];
    const float* Wo      = (const float*)d_in[10];
    const float* bo      = (const float*)d_in[11];
    const float* fg      = (const float*)d_in[12];
    const float* Wl      = (const float*)d_in[13];
    const float* bl      = (const float*)d_in[14];
    const float* W1      = (const float*)d_in[15];
    const float* b1      = (const float*)d_in[16];
    const float* W2      = (const float*)d_in[17];
    const float* b2      = (const float*)d_in[18];
    float* out = (float*)d_out;

    cudaFuncSetAttribute(kA, cudaFuncAttributeMaxDynamicSharedMemorySize, KA_SMEM);
    cudaFuncSetAttribute(k_logits, cudaFuncAttributeMaxDynamicSharedMemorySize, LOGITS_SMEM);

    k_embed<<<(BN * DIM + 255) / 256, 256>>>(kmer, emb, psc);
    k_rot<<<(N * 16 + 255) / 256, 256>>>();

    for (int l = 0; l < DEPTH; l++) {
        const float* Whl = Wh + (long)l * 16 * 64;
        const float* bhl = bh + (long)l * 64;
        const float* Wql = Wqk + (long)l * 16 * 128;
        const float* bql = bqk + (long)l * 128;
        const float* gml = gamma + (long)l * 4 * 128;
        const float* btl = beta + (long)l * 4 * 128;
        kA<<<dim3(2, NG, B), 256, KA_SMEM>>>(norm_g + l, Whl, bhl, Wql, bql, gml, btl);
        kB<<<dim3(8, B), 256>>>(norm_g + l, Whl, bhl, Wql, bql, gml, btl);
        kC<<<dim3(12, B), 256>>>(norm_g + l, Whl, bhl, Wql, bql, gml, btl,
                                 Wo + (long)l * 32 * DIM, bo + (long)l * DIM);
    }

    k_logits<<<BN / 16, 256, LOGITS_SMEM>>>(fg, Wl, bl);
    k_head<<<B, 256>>>(W1, b1, W2, b2, out);
    (void)in_sizes; (void)n_in; (void)out_size;
}

// round 11
// speedup vs baseline: 1.5875x; 1.0148x over previous
#include <cuda_runtime.h>
#include <math.h>

#define B 128
#define N 996
#define BN (B*N)
#define DIM 16
#define QKD 128
#define GSZ 256
#define NG 4
#define DEPTH 8
#define VOC 1024
#define ROTD 32

// ---------------- scratch ----------------
__device__ __align__(16) float g_x[BN*DIM];
__device__ __align__(16) float g_qo[BN*32];          // ungated quad attention out
__device__ __align__(16) float g_linkvp[B*8*128*32]; // only first B*4 slots used now
__device__ float g_rc[N*16];
__device__ float g_rs[N*16];
__device__ float g_hmax[BN];

#define ROT_LC 0.57564627324851142
#define POS_LC 1.1512925464970228

typedef unsigned long long ull;

__device__ __forceinline__ ull pk2(float a, float b) {
    ull r; asm("mov.b64 %0,{%1,%2};" : "=l"(r) : "f"(a), "f"(b)); return r;
}
__device__ __forceinline__ void fma2(ull& d, ull a, ull b) {
    asm("fma.rn.f32x2 %0,%1,%2,%0;" : "+l"(d) : "l"(a), "l"(b));
}
__device__ __forceinline__ float2 up2(ull v) {
    float2 f; asm("mov.b64 {%0,%1},%2;" : "=f"(f.x), "=f"(f.y) : "l"(v)); return f;
}
__device__ __forceinline__ float silu_f(float a) {
    return __fdividef(a, 1.0f + __expf(-a));
}

// proj 8 outputs [u0,u0+8) ; nmA = prev-token normed d0..7, nmB = cur normed d8..15
__device__ __forceinline__ void proj8(const float* nmA, const float* nmB,
                                      const float* __restrict__ W, int ws,
                                      const float* __restrict__ bias, int u0, float* o) {
    #pragma unroll
    for (int j = 0; j < 8; j++) o[j] = bias[u0 + j];
    #pragma unroll
    for (int d = 0; d < 8; d++) { float a = nmA[d];
        #pragma unroll
        for (int j = 0; j < 8; j++) o[j] += a * W[d * ws + u0 + j]; }
    #pragma unroll
    for (int d = 0; d < 8; d++) { float a = nmB[d];
        #pragma unroll
        for (int j = 0; j < 8; j++) o[j] += a * W[(d + 8) * ws + u0 + j]; }
}
// silu + gamma/beta + rotary (chunk-aligned); gb: [0..127]=gamma, [128..255]=beta
__device__ __forceinline__ void gbrot8(float* o, int u0, const float* __restrict__ gb, int pos) {
    #pragma unroll
    for (int jj = 0; jj < 8; jj++) o[jj] = silu_f(o[jj]);
    if (u0 < ROTD) {
        #pragma unroll
        for (int jj = 0; jj < 8; jj += 2) {
            int u = u0 + jj;
            float a = o[jj] * gb[u] + gb[128 + u];
            float b = o[jj+1] * gb[u+1] + gb[128 + u + 1];
            float c = g_rc[pos * 16 + (u >> 1)], s = g_rs[pos * 16 + (u >> 1)];
            o[jj] = a * c - b * s;
            o[jj+1] = b * c + a * s;
        }
    } else {
        #pragma unroll
        for (int jj = 0; jj < 8; jj++) { int u = u0 + jj; o[jj] = o[jj] * gb[u] + gb[128 + u]; }
    }
}

// ---------------- K0 / K0b ----------------
__global__ void k_embed(const int* __restrict__ kmer, const float* __restrict__ emb,
                        const float* __restrict__ ps) {
    int idx = blockIdx.x * blockDim.x + threadIdx.x;
    if (idx >= BN * DIM) return;
    int d = idx & 15;
    int tok = idx >> 4;
    int t = tok % N;
    int j = (d < 8) ? d : d - 8;
    float inv = (float)exp(-(double)j * POS_LC);
    float ang = (float)t * inv;
    float p = (d < 8) ? sinf(ang) : cosf(ang);
    g_x[idx] = emb[kmer[tok] * DIM + d] + p * ps[0];
}
__global__ void k_rot() {
    int idx = blockIdx.x * blockDim.x + threadIdx.x;
    if (idx >= N * 16) return;
    int t = idx >> 4, j = idx & 15;
    float inv = (float)exp(-(double)j * ROT_LC);
    float ang = (float)t * inv;
    g_rc[idx] = cosf(ang);
    g_rs[idx] = sinf(ang);
}

// ---------------- kA: fused norm+proj+quad attention + (qh==0) lin-KV partial ----------------
// dyn smem (floats):
#define OF_SN  0          // [257][17]
#define OF_QS  4372       // [128][132]
#define OF_KT  21268      // [128][66]  transposed K chunk
#define OF_AS  29716      // [128][66]
#define OF_VS  38164      // [64][34]
#define OF_WQK 40340      // [16][128]
#define OF_WV  42388      // [16][32]
#define OF_GBQ 42900      // gamma|beta quad_q
#define OF_GBK 43156      // gamma|beta quad_k
#define OF_BQK 43412
#define OF_BV  43540
#define OF_GB3 43572      // gamma|beta lin_k (row 3)
#define OF_LK  43828      // [64][132] lin_k chunk
#define KA_SMEM ((43828 + 8448) * 4)   // 209104 B

__global__ void __launch_bounds__(256, 1) kA(const float* __restrict__ ng,
        const float* __restrict__ Wh, const float* __restrict__ bh,
        const float* __restrict__ Wqk, const float* __restrict__ bqk,
        const float* __restrict__ gamma, const float* __restrict__ beta) {
    extern __shared__ float s[];
    float* SN = s + OF_SN;  float* QS = s + OF_QS;  float* KT = s + OF_KT;
    float* AS = s + OF_AS;  float* VS = s + OF_VS;  float* WQ = s + OF_WQK;
    float* WV = s + OF_WV;  float* GQ = s + OF_GBQ; float* GK = s + OF_GBK;
    float* BQ = s + OF_BQK; float* BV = s + OF_BV;  float* G3 = s + OF_GB3;
    float* LK = s + OF_LK;
    int tid = threadIdx.x;
    int qh = blockIdx.x, g = blockIdx.y, b = blockIdx.z;
    int gstart = g * GSZ;
    const int bN = b * N;

    for (int i = tid; i < 2048; i += 256) WQ[i] = Wqk[i];
    for (int i = tid; i < 512; i += 256) WV[i] = Wh[(i >> 5) * 64 + (i & 31)];
    if (tid < 128) {
        GQ[tid] = gamma[tid];       GQ[128 + tid] = beta[tid];
        GK[tid] = gamma[256 + tid]; GK[128 + tid] = beta[256 + tid];
        G3[tid] = gamma[384 + tid]; G3[128 + tid] = beta[384 + tid];
        BQ[tid] = bqk[tid];
    }
    if (tid < 32) BV[tid] = bh[tid];
    for (int i = tid; i < 257 * 4; i += 256) {
        int r = i >> 2, d4 = (i & 3) * 4;
        int p = gstart - 1 + r;
        float4 v = make_float4(0, 0, 0, 0);
        if (p >= 0 && p < N) v = *(const float4*)&g_x[(long)(bN + p) * 16 + d4];
        SN[r*17 + d4] = v.x; SN[r*17 + d4+1] = v.y; SN[r*17 + d4+2] = v.z; SN[r*17 + d4+3] = v.w;
    }
    __syncthreads();
    float gng = ng[0];
    for (int i = tid; i < 257; i += 256) {
        float ss = 0;
        #pragma unroll
        for (int d = 0; d < 16; d++) { float v = SN[i*17 + d]; ss += v * v; }
        float scl = gng / fmaxf(sqrtf(ss) * 0.25f, 1e-5f);
        #pragma unroll
        for (int d = 0; d < 16; d++) SN[i*17 + d] *= scl;
    }
    __syncthreads();

    {   // phase1: Q tile (128 q tokens x 128 dims)
        int j = tid >> 1, h = tid & 1;
        int p = gstart + qh * 128 + j;
        int si = qh * 128 + j + 1;
        float nmA[8], nmB[8];
        bool first = (p == 0);
        #pragma unroll
        for (int d = 0; d < 8; d++) {
            nmA[d] = first ? 0.0f : SN[(si - 1) * 17 + d];
            nmB[d] = SN[si * 17 + 8 + d];
        }
        int rp = (p < N) ? p : 0;
        #pragma unroll
        for (int c = 0; c < 8; c++) {
            int u0 = h * 64 + c * 8;
            float o[8];
            proj8(nmA, nmB, WQ, 128, BQ, u0, o);
            gbrot8(o, u0, GQ, rp);
            #pragma unroll
            for (int jj = 0; jj < 8; jj += 2)
                *(float2*)&QS[j * 132 + u0 + jj] = make_float2(o[jj], o[jj+1]);
        }
    }

    ull oacc[8];
    #pragma unroll
    for (int e = 0; e < 8; e++) oacc[e] = 0ull;
    ull lkacc[8];
    #pragma unroll
    for (int e = 0; e < 8; e++) lkacc[e] = 0ull;
    int oi = tid >> 1, eg = (tid & 1) * 16;
    int tx = tid & 7, ty = tid >> 3;
    int dd = tid & 127, e0v = (tid >> 7) * 16;

    for (int ck = 0; ck < 4; ck++) {
        __syncthreads();
        {   // build K chunk (transposed) + V chunk + (qh==0) lin_k chunk
            int t = tid & 63, q4 = tid >> 6;
            int kloc = ck * 64 + t;
            int p = gstart + kloc;
            int si = kloc + 1;
            float nmA[8], nmB[8];
            bool first = (p == 0);
            #pragma unroll
            for (int d = 0; d < 8; d++) {
                nmA[d] = first ? 0.0f : SN[(si - 1) * 17 + d];
                nmB[d] = SN[si * 17 + 8 + d];
            }
            int rp = (p < N) ? p : 0;
            #pragma unroll
            for (int cc = 0; cc < 4; cc++) {
                int u0 = q4 * 32 + cc * 8;
                float o[8];
                proj8(nmA, nmB, WQ, 128, BQ, u0, o);
                gbrot8(o, u0, GK, rp);
                #pragma unroll
                for (int jj = 0; jj < 8; jj++) KT[(u0 + jj) * 66 + t] = o[jj];
            }
            {   int e0 = q4 * 8;
                float o[8];
                proj8(nmA, nmB, WV, 32, BV, e0, o);
                #pragma unroll
                for (int jj = 0; jj < 8; jj++) VS[t * 34 + e0 + jj] = silu_f(o[jj]);
            }
            if (qh == 0) {
                #pragma unroll
                for (int cc = 0; cc < 4; cc++) {
                    int u0 = q4 * 32 + cc * 8;
                    float o[8];
                    proj8(nmA, nmB, WQ, 128, BQ, u0, o);
                    gbrot8(o, u0, G3, rp);
                    #pragma unroll
                    for (int jj = 0; jj < 8; jj++)
                        LK[t * 132 + u0 + jj] = (p < N) ? o[jj] : 0.0f;
                }
            }
        }
        __syncthreads();
        {   // stage A: sim rows (4ty+r) x cols (2tx+16c)
            ull acc[4][4];
            #pragma unroll
            for (int r = 0; r < 4; r++)
                #pragma unroll
                for (int c = 0; c < 4; c++) acc[r][c] = 0ull;
            #pragma unroll 4
            for (int kk = 0; kk < 128; kk++) {
                ull kp[4];
                #pragma unroll
                for (int c = 0; c < 4; c++)
                    kp[c] = *(const ull*)&KT[kk * 66 + 2 * tx + 16 * c];
                #pragma unroll
                for (int r = 0; r < 4; r++) {
                    float qv = QS[(4 * ty + r) * 132 + kk];
                    ull qd = pk2(qv, qv);
                    #pragma unroll
                    for (int c = 0; c < 4; c++) fma2(acc[r][c], qd, kp[c]);
                }
            }
            int kb = gstart + ck * 64;
            #pragma unroll
            for (int r = 0; r < 4; r++) {
                int row = 4 * ty + r;
                #pragma unroll
                for (int c = 0; c < 4; c++) {
                    float2 f = up2(acc[r][c]);
                    int c0 = 2 * tx + 16 * c;
                    float s0 = fmaxf(f.x * (1.0f/256.0f), 0.0f); s0 *= s0;
                    float s1 = fmaxf(f.y * (1.0f/256.0f), 0.0f); s1 *= s1;
                    if (kb + c0     >= N) s0 = 0.0f;
                    if (kb + c0 + 1 >= N) s1 = 0.0f;
                    *(ull*)&AS[row * 66 + c0] = pk2(s0, s1);
                }
            }
        }
        __syncthreads();
        {   // stage B: O[oi][eg..eg+15] += A * V
            #pragma unroll 4
            for (int j = 0; j < 64; j++) {
                float a = AS[oi * 66 + j];
                ull ad = pk2(a, a);
                const ull* vp = (const ull*)&VS[j * 34 + eg];
                #pragma unroll
                for (int e = 0; e < 8; e++) fma2(oacc[e], ad, vp[e]);
            }
        }
        if (qh == 0) {   // lin-KV partial: lkacc[dd][e0v..] += LK[j][dd] * VS[j][e]
            #pragma unroll 4
            for (int j = 0; j < 64; j++) {
                float lv = LK[j * 132 + dd];
                ull ld = pk2(lv, lv);
                const ull* vp = (const ull*)&VS[j * 34 + e0v];
                #pragma unroll
                for (int e = 0; e < 8; e++) fma2(lkacc[e], ld, vp[e]);
            }
        }
    }
    int qp = gstart + qh * 128 + oi;
    if (qp < N) {
        float* dst = &g_qo[(long)(bN + qp) * 32 + eg];
        #pragma unroll
        for (int e = 0; e < 8; e++) { float2 f = up2(oacc[e]); *(float2*)&dst[e * 2] = f; }
    }
    if (qh == 0) {
        float* dst = &g_linkvp[((long)(b * 4 + g) * 128 + dd) * 32 + e0v];
        #pragma unroll
        for (int e = 0; e < 8; e++) { float2 f = up2(lkacc[e]); *(float2*)&dst[e * 2] = f; }
    }
}

// ---------------- kC: fused KV-reduce + lin_out + gate + Wo + residual ----------------
__global__ void __launch_bounds__(256, 2) kC(const float* __restrict__ ng,
        const float* __restrict__ Wh, const float* __restrict__ bh,
        const float* __restrict__ Wqk, const float* __restrict__ bqk,
        const float* __restrict__ gamma, const float* __restrict__ beta,
        const float* __restrict__ Wo, const float* __restrict__ bo) {
    __shared__ __align__(16) float SN[84 * 17];
    __shared__ __align__(16) float SKV[4096];
    __shared__ __align__(16) float WQ[2048];
    __shared__ __align__(16) float WG[512];
    __shared__ __align__(16) float GB[256];
    __shared__ __align__(16) float BQ2[128];
    __shared__ __align__(16) float BG[32];
    __shared__ __align__(16) float SWO[512];
    __shared__ __align__(16) float SBO[16];
    __shared__ __align__(16) float OVS[8][32];
    int tid = threadIdx.x;
    int ch = blockIdx.x, b = blockIdx.y;
    const int bN = b * N;
    int t0 = ch * 83;

    for (int i = tid; i < 2048; i += 256) WQ[i] = Wqk[i];
    for (int i = tid; i < 512; i += 256) {
        WG[i] = Wh[(i >> 5) * 64 + 32 + (i & 31)];
        SWO[i] = Wo[i];
    }
    if (tid < 128) {
        GB[tid] = gamma[128 + tid]; GB[128 + tid] = beta[128 + tid];
        BQ2[tid] = bqk[tid];
    }
    if (tid < 32) BG[tid] = bh[32 + tid];
    if (tid < 16) SBO[tid] = bo[tid];
    const float inv_n = 1.0f / (float)N;
    for (int i = tid; i < 1024; i += 256) {
        float4 ssum = make_float4(0, 0, 0, 0);
        #pragma unroll
        for (int k2 = 0; k2 < 4; k2++) {
            float4 p = ((const float4*)&g_linkvp[(long)(b * 4 + k2) * 4096])[i];
            ssum.x += p.x; ssum.y += p.y; ssum.z += p.z; ssum.w += p.w;
        }
        ((float4*)SKV)[i] = make_float4(ssum.x * inv_n, ssum.y * inv_n, ssum.z * inv_n, ssum.w * inv_n);
    }
    for (int i = tid; i < 84 * 4; i += 256) {
        int r = i >> 2, d4 = (i & 3) * 4;
        int p = t0 - 1 + r;
        float4 v = make_float4(0, 0, 0, 0);
        if (p >= 0 && p < N) v = *(const float4*)&g_x[(long)(bN + p) * 16 + d4];
        SN[r*17 + d4] = v.x; SN[r*17 + d4+1] = v.y; SN[r*17 + d4+2] = v.z; SN[r*17 + d4+3] = v.w;
    }
    __syncthreads();
    float gng = ng[0];
    for (int i = tid; i < 84; i += 256) {
        float ss = 0;
        #pragma unroll
        for (int d = 0; d < 16; d++) { float v = SN[i*17 + d]; ss += v * v; }
        float scl = gng / fmaxf(sqrtf(ss) * 0.25f, 1e-5f);
        #pragma unroll
        for (int d = 0; d < 16; d++) SN[i*17 + d] *= scl;
    }
    __syncthreads();

    int w = tid >> 5, lane = tid & 31;
    for (int tok = t0 + w; tok < t0 + 83; tok += 8) {
        int si = tok - t0 + 1;
        bool first = (tok == 0);
        float nmA[8], nmB[8];
        #pragma unroll
        for (int d = 0; d < 8; d++) {
            nmA[d] = first ? 0.0f : SN[(si - 1) * 17 + d];
            nmB[d] = SN[si * 17 + 8 + d];
        }
        float lq4[4];
        #pragma unroll
        for (int j = 0; j < 4; j++) {
            int u = lane + 32 * j;
            float o = BQ2[u];
            #pragma unroll
            for (int d = 0; d < 8; d++) o += nmA[d] * WQ[d * 128 + u];
            #pragma unroll
            for (int d = 0; d < 8; d++) o += nmB[d] * WQ[(d + 8) * 128 + u];
            o = silu_f(o);
            o = o * GB[u] + GB[128 + u];
            if (j == 0) {
                float c = g_rc[tok * 16 + (lane >> 1)], sn2 = g_rs[tok * 16 + (lane >> 1)];
                float part = __shfl_xor_sync(0xffffffffu, o, 1);
                o = (lane & 1) ? (o * c + part * sn2) : (o * c - part * sn2);
            }
            lq4[j] = o;
        }
        float gt;
        {   float o = BG[lane];
            #pragma unroll
            for (int d = 0; d < 8; d++) o += nmA[d] * WG[d * 32 + lane];
            #pragma unroll
            for (int d = 0; d < 8; d++) o += nmB[d] * WG[(d + 8) * 32 + lane];
            gt = silu_f(o);
        }
        float acc = g_qo[(long)(bN + tok) * 32 + lane];
        #pragma unroll
        for (int j = 0; j < 4; j++) {
            #pragma unroll
            for (int src = 0; src < 32; src++) {
                float lv = __shfl_sync(0xffffffffu, lq4[j], src);
                acc += lv * SKV[(src + 32 * j) * 32 + lane];
            }
        }
        acc *= gt;
        OVS[w][lane] = acc;
        __syncwarp();
        if (lane < 16) {
            float y = SBO[lane];
            #pragma unroll
            for (int e = 0; e < 32; e++) y += OVS[w][e] * SWO[e * 16 + lane];
            g_x[(long)(bN + tok) * 16 + lane] += y;
        }
        __syncwarp();
    }
}

// ---------------- k_logits / k_head ----------------
#define LOGITS_SMEM ((16*1024 + 1024 + 16*16) * 4)
__global__ void k_logits(const float* __restrict__ fg, const float* __restrict__ Wl,
                         const float* __restrict__ blv) {
    extern __shared__ float sm[];
    float* sW = sm;
    float* sb = sW + 16 * 1024;
    float* xn = sb + 1024;
    __shared__ float wred[8];
    __shared__ float xs[16];
    int tid = threadIdx.x;
    int base = blockIdx.x * 16;
    for (int i = tid; i < (16 * 1024) / 4; i += 256)
        ((float4*)sW)[i] = ((const float4*)Wl)[i];
    for (int i = tid; i < 1024; i += 256) sb[i] = blv[i];
    {   int tt = tid >> 4, d = tid & 15;
        xn[tt * 16 + d] = g_x[(long)(base + tt) * DIM + d];
    }
    __syncthreads();
    if (tid < 16) {
        float ss = 0;
        #pragma unroll
        for (int d = 0; d < 16; d++) { float v = xn[tid * 16 + d]; ss += v * v; }
        xs[tid] = fg[0] / fmaxf(sqrtf(ss) * 0.25f, 1e-5f);
    }
    __syncthreads();
    {   int tt = tid >> 4, d = tid & 15;
        xn[tt * 16 + d] *= xs[tt];
    }
    __syncthreads();
    int warp = tid >> 5, lane = tid & 31;
    int v0 = tid * 4;
    for (int tt = 0; tt < 16; tt++) {
        float s0 = sb[v0], s1 = sb[v0+1], s2 = sb[v0+2], s3 = sb[v0+3];
        #pragma unroll
        for (int d = 0; d < 16; d++) {
            float xv = xn[tt * 16 + d];
            float4 wv = *(const float4*)&sW[d * 1024 + v0];
            s0 += xv * wv.x; s1 += xv * wv.y; s2 += xv * wv.z; s3 += xv * wv.w;
        }
        float m = fmaxf(fmaxf(s0, s1), fmaxf(s2, s3));
        #pragma unroll
        for (int off = 16; off > 0; off >>= 1)
            m = fmaxf(m, __shfl_xor_sync(0xffffffff, m, off));
        if (lane == 0) wred[warp] = m;
        __syncthreads();
        if (tid == 0) {
            float mm = wred[0];
            #pragma unroll
            for (int j = 1; j < 8; j++) mm = fmaxf(mm, wred[j]);
            g_hmax[base + tt] = mm;
        }
        __syncthreads();
    }
}
__global__ void k_head(const float* __restrict__ W1, const float* __restrict__ b1,
                       const float* __restrict__ W2, const float* __restrict__ b2,
                       float* __restrict__ out) {
    __shared__ float red[8][32];
    __shared__ float rr[32];
    int tid = threadIdx.x;
    int b = blockIdx.x;
    int col = tid & 31, seg = tid >> 5;
    float acc = 0.0f;
    int t0 = seg * 125;
    int t1 = min(t0 + 125, N);
    for (int t = t0; t < t1; t++)
        acc += g_hmax[(long)b * N + t] * W1[t * 32 + col];
    red[seg][col] = acc;
    __syncthreads();
    if (tid < 32) {
        float ss = b1[tid];
        #pragma unroll
        for (int k = 0; k < 8; k++) ss += red[k][tid];
        rr[tid] = fmaxf(ss, 0.0f);
    }
    __syncthreads();
    if (tid == 0) {
        float o = b2[0];
        #pragma unroll
        for (int j = 0; j < 32; j++) o += rr[j] * W2[j];
        out[b] = o;
    }
}

// ---------------- launch ----------------
extern "C" void kernel_launch(void* const* d_in, const int* in_sizes, int n_in,
                              void* d_out, int out_size) {
    const int*   kmer    = (const int*)  d_in[0];
    const float* emb     = (const float*)d_in[1];
    const float* psc     = (const float*)d_in[2];
    const float* norm_g  = (const float*)d_in[3];
    const float* Wh      = (const float*)d_in[4];
    const float* bh      = (const float*)d_in[5];
    const float* Wqk     = (const float*)d_in[6];
    const float* bqk     = (const float*)d_in[7];
    const float* gamma   = (const float*)d_in[8];
    const float* beta    = (const float*)d_in[9];
    const float* Wo      = (const float*)d_in[10];
    const float* bo      = (const float*)d_in[11];
    const float* fg      = (const float*)d_in[12];
    const float* Wl      = (const float*)d_in[13];
    const float* bl      = (const float*)d_in[14];
    const float* W1      = (const float*)d_in[15];
    const float* b1      = (const float*)d_in[16];
    const float* W2      = (const float*)d_in[17];
    const float* b2      = (const float*)d_in[18];
    float* out = (float*)d_out;

    cudaFuncSetAttribute(kA, cudaFuncAttributeMaxDynamicSharedMemorySize, KA_SMEM);
    cudaFuncSetAttribute(k_logits, cudaFuncAttributeMaxDynamicSharedMemorySize, LOGITS_SMEM);

    k_embed<<<(BN * DIM + 255) / 256, 256>>>(kmer, emb, psc);
    k_rot<<<(N * 16 + 255) / 256, 256>>>();

    for (int l = 0; l < DEPTH; l++) {
        const float* Whl = Wh + (long)l * 16 * 64;
        const float* bhl = bh + (long)l * 64;
        const float* Wql = Wqk + (long)l * 16 * 128;
        const float* bql = bqk + (long)l * 128;
        const float* gml = gamma + (long)l * 4 * 128;
        const float* btl = beta + (long)l * 4 * 128;
        kA<<<dim3(2, NG, B), 256, KA_SMEM>>>(norm_g + l, Whl, bhl, Wql, bql, gml, btl);
        kC<<<dim3(12, B), 256>>>(norm_g + l, Whl, bhl, Wql, bql, gml, btl,
                                 Wo + (long)l * 32 * DIM, bo + (long)l * DIM);
    }

    k_logits<<<BN / 16, 256, LOGITS_SMEM>>>(fg, Wl, bl);
    k_head<<<B, 256>>>(W1, b1, W2, b2, out);
    (void)in_sizes; (void)n_in; (void)out_size;
}

// round 12
// speedup vs baseline: 1.6333x; 1.0288x over previous
#include <cuda_runtime.h>
#include <math.h>

#define B 128
#define N 996
#define BN (B*N)
#define DIM 16
#define QKD 128
#define GSZ 256
#define NG 4
#define DEPTH 8
#define VOC 1024
#define ROTD 32

// ---------------- scratch ----------------
__device__ __align__(16) float g_x[BN*DIM];
__device__ __align__(16) float g_qo[BN*32];          // ungated quad attention out
__device__ __align__(16) float g_linkvp[B*8*128*32];
__device__ float g_rc[N*16];
__device__ float g_rs[N*16];
__device__ float g_hmax[BN];

#define ROT_LC 0.57564627324851142
#define POS_LC 1.1512925464970228

typedef unsigned long long ull;

__device__ __forceinline__ ull pk2(float a, float b) {
    ull r; asm("mov.b64 %0,{%1,%2};" : "=l"(r) : "f"(a), "f"(b)); return r;
}
__device__ __forceinline__ void fma2(ull& d, ull a, ull b) {
    asm("fma.rn.f32x2 %0,%1,%2,%0;" : "+l"(d) : "l"(a), "l"(b));
}
__device__ __forceinline__ float2 up2(ull v) {
    float2 f; asm("mov.b64 {%0,%1},%2;" : "=f"(f.x), "=f"(f.y) : "l"(v)); return f;
}
__device__ __forceinline__ float silu_f(float a) {
    return __fdividef(a, 1.0f + __expf(-a));
}

// proj 8 outputs [u0,u0+8) ; nmA = prev-token normed d0..7, nmB = cur normed d8..15
__device__ __forceinline__ void proj8(const float* nmA, const float* nmB,
                                      const float* __restrict__ W, int ws,
                                      const float* __restrict__ bias, int u0, float* o) {
    #pragma unroll
    for (int j = 0; j < 8; j++) o[j] = bias[u0 + j];
    #pragma unroll
    for (int d = 0; d < 8; d++) { float a = nmA[d];
        #pragma unroll
        for (int j = 0; j < 8; j++) o[j] += a * W[d * ws + u0 + j]; }
    #pragma unroll
    for (int d = 0; d < 8; d++) { float a = nmB[d];
        #pragma unroll
        for (int j = 0; j < 8; j++) o[j] += a * W[(d + 8) * ws + u0 + j]; }
}
// silu + gamma/beta + rotary (chunk-aligned); gb: [0..127]=gamma, [128..255]=beta
__device__ __forceinline__ void gbrot8(float* o, int u0, const float* __restrict__ gb, int pos) {
    #pragma unroll
    for (int jj = 0; jj < 8; jj++) o[jj] = silu_f(o[jj]);
    if (u0 < ROTD) {
        #pragma unroll
        for (int jj = 0; jj < 8; jj += 2) {
            int u = u0 + jj;
            float a = o[jj] * gb[u] + gb[128 + u];
            float b = o[jj+1] * gb[u+1] + gb[128 + u + 1];
            float c = g_rc[pos * 16 + (u >> 1)], s = g_rs[pos * 16 + (u >> 1)];
            o[jj] = a * c - b * s;
            o[jj+1] = b * c + a * s;
        }
    } else {
        #pragma unroll
        for (int jj = 0; jj < 8; jj++) { int u = u0 + jj; o[jj] = o[jj] * gb[u] + gb[128 + u]; }
    }
}

// ---------------- K0 / K0b ----------------
__global__ void k_embed(const int* __restrict__ kmer, const float* __restrict__ emb,
                        const float* __restrict__ ps) {
    int idx = blockIdx.x * blockDim.x + threadIdx.x;
    if (idx >= BN * DIM) return;
    int d = idx & 15;
    int tok = idx >> 4;
    int t = tok % N;
    int j = (d < 8) ? d : d - 8;
    float inv = (float)exp(-(double)j * POS_LC);
    float ang = (float)t * inv;
    float p = (d < 8) ? sinf(ang) : cosf(ang);
    g_x[idx] = emb[kmer[tok] * DIM + d] + p * ps[0];
}
__global__ void k_rot() {
    int idx = blockIdx.x * blockDim.x + threadIdx.x;
    if (idx >= N * 16) return;
    int t = idx >> 4, j = idx & 15;
    float inv = (float)exp(-(double)j * ROT_LC);
    float ang = (float)t * inv;
    g_rc[idx] = cosf(ang);
    g_rs[idx] = sinf(ang);
}

// ---------------- kA: fused norm+proj+quad attention + balanced lin-KV partial ----------------
// dyn smem (floats):
#define OF_SN  0          // [257][17]
#define OF_QS  4372       // [128][132]
#define OF_KT  21268      // [128][66]  transposed K chunk
#define OF_AS  29716      // [128][66]
#define OF_VS  38164      // [64][34]
#define OF_WQK 40340      // [16][128]
#define OF_WV  42388      // [16][32]
#define OF_GBQ 42900      // gamma|beta quad_q
#define OF_GBK 43156      // gamma|beta quad_k
#define OF_BQK 43412
#define OF_BV  43540
#define OF_GB3 43572      // gamma|beta lin_k (row 3)
#define OF_LK  43828      // [64][132] lin_k chunk
#define KA_SMEM ((43828 + 8448) * 4)   // 209104 B

__global__ void __launch_bounds__(256, 1) kA(const float* __restrict__ ng,
        const float* __restrict__ Wh, const float* __restrict__ bh,
        const float* __restrict__ Wqk, const float* __restrict__ bqk,
        const float* __restrict__ gamma, const float* __restrict__ beta) {
    extern __shared__ float s[];
    float* SN = s + OF_SN;  float* QS = s + OF_QS;  float* KT = s + OF_KT;
    float* AS = s + OF_AS;  float* VS = s + OF_VS;  float* WQ = s + OF_WQK;
    float* WV = s + OF_WV;  float* GQ = s + OF_GBQ; float* GK = s + OF_GBK;
    float* BQ = s + OF_BQK; float* BV = s + OF_BV;  float* G3 = s + OF_GB3;
    float* LK = s + OF_LK;
    int tid = threadIdx.x;
    int qh = blockIdx.x, g = blockIdx.y, b = blockIdx.z;
    int gstart = g * GSZ;
    const int bN = b * N;

    for (int i = tid; i < 2048; i += 256) WQ[i] = Wqk[i];
    for (int i = tid; i < 512; i += 256) WV[i] = Wh[(i >> 5) * 64 + (i & 31)];
    if (tid < 128) {
        GQ[tid] = gamma[tid];       GQ[128 + tid] = beta[tid];
        GK[tid] = gamma[256 + tid]; GK[128 + tid] = beta[256 + tid];
        G3[tid] = gamma[384 + tid]; G3[128 + tid] = beta[384 + tid];
        BQ[tid] = bqk[tid];
    }
    if (tid < 32) BV[tid] = bh[tid];
    for (int i = tid; i < 257 * 4; i += 256) {
        int r = i >> 2, d4 = (i & 3) * 4;
        int p = gstart - 1 + r;
        float4 v = make_float4(0, 0, 0, 0);
        if (p >= 0 && p < N) v = *(const float4*)&g_x[(long)(bN + p) * 16 + d4];
        SN[r*17 + d4] = v.x; SN[r*17 + d4+1] = v.y; SN[r*17 + d4+2] = v.z; SN[r*17 + d4+3] = v.w;
    }
    __syncthreads();
    float gng = ng[0];
    for (int i = tid; i < 257; i += 256) {
        float ss = 0;
        #pragma unroll
        for (int d = 0; d < 16; d++) { float v = SN[i*17 + d]; ss += v * v; }
        float scl = gng / fmaxf(sqrtf(ss) * 0.25f, 1e-5f);
        #pragma unroll
        for (int d = 0; d < 16; d++) SN[i*17 + d] *= scl;
    }
    __syncthreads();

    {   // phase1: Q tile (128 q tokens x 128 dims)
        int j = tid >> 1, h = tid & 1;
        int p = gstart + qh * 128 + j;
        int si = qh * 128 + j + 1;
        float nmA[8], nmB[8];
        bool first = (p == 0);
        #pragma unroll
        for (int d = 0; d < 8; d++) {
            nmA[d] = first ? 0.0f : SN[(si - 1) * 17 + d];
            nmB[d] = SN[si * 17 + 8 + d];
        }
        int rp = (p < N) ? p : 0;
        #pragma unroll
        for (int c = 0; c < 8; c++) {
            int u0 = h * 64 + c * 8;
            float o[8];
            proj8(nmA, nmB, WQ, 128, BQ, u0, o);
            gbrot8(o, u0, GQ, rp);
            #pragma unroll
            for (int jj = 0; jj < 8; jj += 2)
                *(float2*)&QS[j * 132 + u0 + jj] = make_float2(o[jj], o[jj+1]);
        }
    }

    ull oacc[8];
    #pragma unroll
    for (int e = 0; e < 8; e++) oacc[e] = 0ull;
    ull lkacc[8];
    #pragma unroll
    for (int e = 0; e < 8; e++) lkacc[e] = 0ull;
    int oi = tid >> 1, eg = (tid & 1) * 16;
    int tx = tid & 7, ty = tid >> 3;
    int dd = tid & 127, e0v = (tid >> 7) * 16;

    for (int ck = 0; ck < 4; ck++) {
        bool mylin = (qh == (ck >> 1));   // each CTA owns 2 of the 4 chunks
        __syncthreads();
        {   // build K chunk (transposed) + V chunk + (owned) lin_k chunk
            int t = tid & 63, q4 = tid >> 6;
            int kloc = ck * 64 + t;
            int p = gstart + kloc;
            int si = kloc + 1;
            float nmA[8], nmB[8];
            bool first = (p == 0);
            #pragma unroll
            for (int d = 0; d < 8; d++) {
                nmA[d] = first ? 0.0f : SN[(si - 1) * 17 + d];
                nmB[d] = SN[si * 17 + 8 + d];
            }
            int rp = (p < N) ? p : 0;
            #pragma unroll
            for (int cc = 0; cc < 4; cc++) {
                int u0 = q4 * 32 + cc * 8;
                float o[8];
                proj8(nmA, nmB, WQ, 128, BQ, u0, o);
                gbrot8(o, u0, GK, rp);
                #pragma unroll
                for (int jj = 0; jj < 8; jj++) KT[(u0 + jj) * 66 + t] = o[jj];
            }
            {   int e0 = q4 * 8;
                float o[8];
                proj8(nmA, nmB, WV, 32, BV, e0, o);
                #pragma unroll
                for (int jj = 0; jj < 8; jj++) VS[t * 34 + e0 + jj] = silu_f(o[jj]);
            }
            if (mylin) {
                #pragma unroll
                for (int cc = 0; cc < 4; cc++) {
                    int u0 = q4 * 32 + cc * 8;
                    float o[8];
                    proj8(nmA, nmB, WQ, 128, BQ, u0, o);
                    gbrot8(o, u0, G3, rp);
                    #pragma unroll
                    for (int jj = 0; jj < 8; jj++)
                        LK[t * 132 + u0 + jj] = (p < N) ? o[jj] : 0.0f;
                }
            }
        }
        __syncthreads();
        {   // stage A: sim rows (4ty+r) x cols (2tx+16c)
            ull acc[4][4];
            #pragma unroll
            for (int r = 0; r < 4; r++)
                #pragma unroll
                for (int c = 0; c < 4; c++) acc[r][c] = 0ull;
            #pragma unroll 4
            for (int kk = 0; kk < 128; kk++) {
                ull kp[4];
                #pragma unroll
                for (int c = 0; c < 4; c++)
                    kp[c] = *(const ull*)&KT[kk * 66 + 2 * tx + 16 * c];
                #pragma unroll
                for (int r = 0; r < 4; r++) {
                    float qv = QS[(4 * ty + r) * 132 + kk];
                    ull qd = pk2(qv, qv);
                    #pragma unroll
                    for (int c = 0; c < 4; c++) fma2(acc[r][c], qd, kp[c]);
                }
            }
            int kb = gstart + ck * 64;
            #pragma unroll
            for (int r = 0; r < 4; r++) {
                int row = 4 * ty + r;
                #pragma unroll
                for (int c = 0; c < 4; c++) {
                    float2 f = up2(acc[r][c]);
                    int c0 = 2 * tx + 16 * c;
                    float s0 = fmaxf(f.x * (1.0f/256.0f), 0.0f); s0 *= s0;
                    float s1 = fmaxf(f.y * (1.0f/256.0f), 0.0f); s1 *= s1;
                    if (kb + c0     >= N) s0 = 0.0f;
                    if (kb + c0 + 1 >= N) s1 = 0.0f;
                    *(ull*)&AS[row * 66 + c0] = pk2(s0, s1);
                }
            }
        }
        __syncthreads();
        {   // stage B: O[oi][eg..eg+15] += A * V
            #pragma unroll 4
            for (int j = 0; j < 64; j++) {
                float a = AS[oi * 66 + j];
                ull ad = pk2(a, a);
                const ull* vp = (const ull*)&VS[j * 34 + eg];
                #pragma unroll
                for (int e = 0; e < 8; e++) fma2(oacc[e], ad, vp[e]);
            }
        }
        if (mylin) {   // lin-KV partial for owned chunk
            #pragma unroll 4
            for (int j = 0; j < 64; j++) {
                float lv = LK[j * 132 + dd];
                ull ld = pk2(lv, lv);
                const ull* vp = (const ull*)&VS[j * 34 + e0v];
                #pragma unroll
                for (int e = 0; e < 8; e++) fma2(lkacc[e], ld, vp[e]);
            }
        }
    }
    int qp = gstart + qh * 128 + oi;
    if (qp < N) {
        float* dst = &g_qo[(long)(bN + qp) * 32 + eg];
        #pragma unroll
        for (int e = 0; e < 8; e++) { float2 f = up2(oacc[e]); *(float2*)&dst[e * 2] = f; }
    }
    {   // one partial per (g, qh) pair
        float* dst = &g_linkvp[((long)(b * 8 + g * 2 + qh) * 128 + dd) * 32 + e0v];
        #pragma unroll
        for (int e = 0; e < 8; e++) { float2 f = up2(lkacc[e]); *(float2*)&dst[e * 2] = f; }
    }
}

// ---------------- kC: fused KV-reduce + lin_out + gate + Wo + residual ----------------
__global__ void __launch_bounds__(256, 2) kC(const float* __restrict__ ng,
        const float* __restrict__ Wh, const float* __restrict__ bh,
        const float* __restrict__ Wqk, const float* __restrict__ bqk,
        const float* __restrict__ gamma, const float* __restrict__ beta,
        const float* __restrict__ Wo, const float* __restrict__ bo) {
    __shared__ __align__(16) float SN[84 * 17];
    __shared__ __align__(16) float SKV[4096];
    __shared__ __align__(16) float WQ[2048];
    __shared__ __align__(16) float WG[512];
    __shared__ __align__(16) float GB[256];
    __shared__ __align__(16) float BQ2[128];
    __shared__ __align__(16) float BG[32];
    __shared__ __align__(16) float SWO[512];
    __shared__ __align__(16) float SBO[16];
    __shared__ __align__(16) float OVS[8][32];
    int tid = threadIdx.x;
    int ch = blockIdx.x, b = blockIdx.y;
    const int bN = b * N;
    int t0 = ch * 83;

    for (int i = tid; i < 2048; i += 256) WQ[i] = Wqk[i];
    for (int i = tid; i < 512; i += 256) {
        WG[i] = Wh[(i >> 5) * 64 + 32 + (i & 31)];
        SWO[i] = Wo[i];
    }
    if (tid < 128) {
        GB[tid] = gamma[128 + tid]; GB[128 + tid] = beta[128 + tid];
        BQ2[tid] = bqk[tid];
    }
    if (tid < 32) BG[tid] = bh[32 + tid];
    if (tid < 16) SBO[tid] = bo[tid];
    const float inv_n = 1.0f / (float)N;
    for (int i = tid; i < 1024; i += 256) {
        float4 ssum = make_float4(0, 0, 0, 0);
        #pragma unroll
        for (int k2 = 0; k2 < 8; k2++) {
            float4 p = ((const float4*)&g_linkvp[(long)(b * 8 + k2) * 4096])[i];
            ssum.x += p.x; ssum.y += p.y; ssum.z += p.z; ssum.w += p.w;
        }
        ((float4*)SKV)[i] = make_float4(ssum.x * inv_n, ssum.y * inv_n, ssum.z * inv_n, ssum.w * inv_n);
    }
    for (int i = tid; i < 84 * 4; i += 256) {
        int r = i >> 2, d4 = (i & 3) * 4;
        int p = t0 - 1 + r;
        float4 v = make_float4(0, 0, 0, 0);
        if (p >= 0 && p < N) v = *(const float4*)&g_x[(long)(bN + p) * 16 + d4];
        SN[r*17 + d4] = v.x; SN[r*17 + d4+1] = v.y; SN[r*17 + d4+2] = v.z; SN[r*17 + d4+3] = v.w;
    }
    __syncthreads();
    float gng = ng[0];
    for (int i = tid; i < 84; i += 256) {
        float ss = 0;
        #pragma unroll
        for (int d = 0; d < 16; d++) { float v = SN[i*17 + d]; ss += v * v; }
        float scl = gng / fmaxf(sqrtf(ss) * 0.25f, 1e-5f);
        #pragma unroll
        for (int d = 0; d < 16; d++) SN[i*17 + d] *= scl;
    }
    __syncthreads();

    int w = tid >> 5, lane = tid & 31;
    for (int tok = t0 + w; tok < t0 + 83; tok += 8) {
        int si = tok - t0 + 1;
        bool first = (tok == 0);
        float nmA[8], nmB[8];
        #pragma unroll
        for (int d = 0; d < 8; d++) {
            nmA[d] = first ? 0.0f : SN[(si - 1) * 17 + d];
            nmB[d] = SN[si * 17 + 8 + d];
        }
        float lq4[4];
        #pragma unroll
        for (int j = 0; j < 4; j++) {
            int u = lane + 32 * j;
            float o = BQ2[u];
            #pragma unroll
            for (int d = 0; d < 8; d++) o += nmA[d] * WQ[d * 128 + u];
            #pragma unroll
            for (int d = 0; d < 8; d++) o += nmB[d] * WQ[(d + 8) * 128 + u];
            o = silu_f(o);
            o = o * GB[u] + GB[128 + u];
            if (j == 0) {
                float c = g_rc[tok * 16 + (lane >> 1)], sn2 = g_rs[tok * 16 + (lane >> 1)];
                float part = __shfl_xor_sync(0xffffffffu, o, 1);
                o = (lane & 1) ? (o * c + part * sn2) : (o * c - part * sn2);
            }
            lq4[j] = o;
        }
        float gt;
        {   float o = BG[lane];
            #pragma unroll
            for (int d = 0; d < 8; d++) o += nmA[d] * WG[d * 32 + lane];
            #pragma unroll
            for (int d = 0; d < 8; d++) o += nmB[d] * WG[(d + 8) * 32 + lane];
            gt = silu_f(o);
        }
        // lin_out with 8 independent partial accumulators (chain depth 16)
        float accs[4];
        #pragma unroll
        for (int j = 0; j < 4; j++) {
            float pa = 0.0f, pb = 0.0f;
            #pragma unroll
            for (int s2 = 0; s2 < 16; s2++) {
                float lva = __shfl_sync(0xffffffffu, lq4[j], 2 * s2);
                float lvb = __shfl_sync(0xffffffffu, lq4[j], 2 * s2 + 1);
                pa += lva * SKV[(2 * s2 + 32 * j) * 32 + lane];
                pb += lvb * SKV[(2 * s2 + 1 + 32 * j) * 32 + lane];
            }
            accs[j] = pa + pb;
        }
        float acc = g_qo[(long)(bN + tok) * 32 + lane]
                  + ((accs[0] + accs[1]) + (accs[2] + accs[3]));
        acc *= gt;
        OVS[w][lane] = acc;
        __syncwarp();
        if (lane < 16) {
            float y = SBO[lane];
            #pragma unroll
            for (int e = 0; e < 32; e++) y += OVS[w][e] * SWO[e * 16 + lane];
            g_x[(long)(bN + tok) * 16 + lane] += y;
        }
        __syncwarp();
    }
}

// ---------------- k_logits / k_head ----------------
#define LOGITS_SMEM ((16*1024 + 1024 + 16*16) * 4)
__global__ void k_logits(const float* __restrict__ fg, const float* __restrict__ Wl,
                         const float* __restrict__ blv) {
    extern __shared__ float sm[];
    float* sW = sm;
    float* sb = sW + 16 * 1024;
    float* xn = sb + 1024;
    __shared__ float wred[8];
    __shared__ float xs[16];
    int tid = threadIdx.x;
    int base = blockIdx.x * 16;
    for (int i = tid; i < (16 * 1024) / 4; i += 256)
        ((float4*)sW)[i] = ((const float4*)Wl)[i];
    for (int i = tid; i < 1024; i += 256) sb[i] = blv[i];
    {   int tt = tid >> 4, d = tid & 15;
        xn[tt * 16 + d] = g_x[(long)(base + tt) * DIM + d];
    }
    __syncthreads();
    if (tid < 16) {
        float ss = 0;
        #pragma unroll
        for (int d = 0; d < 16; d++) { float v = xn[tid * 16 + d]; ss += v * v; }
        xs[tid] = fg[0] / fmaxf(sqrtf(ss) * 0.25f, 1e-5f);
    }
    __syncthreads();
    {   int tt = tid >> 4, d = tid & 15;
        xn[tt * 16 + d] *= xs[tt];
    }
    __syncthreads();
    int warp = tid >> 5, lane = tid & 31;
    int v0 = tid * 4;
    for (int tt = 0; tt < 16; tt++) {
        float s0 = sb[v0], s1 = sb[v0+1], s2 = sb[v0+2], s3 = sb[v0+3];
        #pragma unroll
        for (int d = 0; d < 16; d++) {
            float xv = xn[tt * 16 + d];
            float4 wv = *(const float4*)&sW[d * 1024 + v0];
            s0 += xv * wv.x; s1 += xv * wv.y; s2 += xv * wv.z; s3 += xv * wv.w;
        }
        float m = fmaxf(fmaxf(s0, s1), fmaxf(s2, s3));
        #pragma unroll
        for (int off = 16; off > 0; off >>= 1)
            m = fmaxf(m, __shfl_xor_sync(0xffffffff, m, off));
        if (lane == 0) wred[warp] = m;
        __syncthreads();
        if (tid == 0) {
            float mm = wred[0];
            #pragma unroll
            for (int j = 1; j < 8; j++) mm = fmaxf(mm, wred[j]);
            g_hmax[base + tt] = mm;
        }
        __syncthreads();
    }
}
__global__ void k_head(const float* __restrict__ W1, const float* __restrict__ b1,
                       const float* __restrict__ W2, const float* __restrict__ b2,
                       float* __restrict__ out) {
    __shared__ float red[8][32];
    __shared__ float rr[32];
    int tid = threadIdx.x;
    int b = blockIdx.x;
    int col = tid & 31, seg = tid >> 5;
    float acc = 0.0f;
    int t0 = seg * 125;
    int t1 = min(t0 + 125, N);
    for (int t = t0; t < t1; t++)
        acc += g_hmax[(long)b * N + t] * W1[t * 32 + col];
    red[seg][col] = acc;
    __syncthreads();
    if (tid < 32) {
        float ss = b1[tid];
        #pragma unroll
        for (int k = 0; k < 8; k++) ss += red[k][tid];
        rr[tid] = fmaxf(ss, 0.0f);
    }
    __syncthreads();
    if (tid == 0) {
        float o = b2[0];
        #pragma unroll
        for (int j = 0; j < 32; j++) o += rr[j] * W2[j];
        out[b] = o;
    }
}

// ---------------- launch ----------------
extern "C" void kernel_launch(void* const* d_in, const int* in_sizes, int n_in,
                              void* d_out, int out_size) {
    const int*   kmer    = (const int*)  d_in[0];
    const float* emb     = (const float*)d_in[1];
    const float* psc     = (const float*)d_in[2];
    const float* norm_g  = (const float*)d_in[3];
    const float* Wh      = (const float*)d_in[4];
    const float* bh      = (const float*)d_in[5];
    const float* Wqk     = (const float*)d_in[6];
    const float* bqk     = (const float*)d_in[7];
    const float* gamma   = (const float*)d_in[8];
    const float* beta    = (const float*)d_in[9];
    const float* Wo      = (const float*)d_in[10];
    const float* bo      = (const float*)d_in[11];
    const float* fg      = (const float*)d_in[12];
    const float* Wl      = (const float*)d_in[13];
    const float* bl      = (const float*)d_in[14];
    const float* W1      = (const float*)d_in[15];
    const float* b1      = (const float*)d_in[16];
    const float* W2      = (const float*)d_in[17];
    const float* b2      = (const float*)d_in[18];
    float* out = (float*)d_out;

    cudaFuncSetAttribute(kA, cudaFuncAttributeMaxDynamicSharedMemorySize, KA_SMEM);
    cudaFuncSetAttribute(k_logits, cudaFuncAttributeMaxDynamicSharedMemorySize, LOGITS_SMEM);

    k_embed<<<(BN * DIM + 255) / 256, 256>>>(kmer, emb, psc);
    k_rot<<<(N * 16 + 255) / 256, 256>>>();

    for (int l = 0; l < DEPTH; l++) {
        const float* Whl = Wh + (long)l * 16 * 64;
        const float* bhl = bh + (long)l * 64;
        const float* Wql = Wqk + (long)l * 16 * 128;
        const float* bql = bqk + (long)l * 128;
        const float* gml = gamma + (long)l * 4 * 128;
        const float* btl = beta + (long)l * 4 * 128;
        kA<<<dim3(2, NG, B), 256, KA_SMEM>>>(norm_g + l, Whl, bhl, Wql, bql, gml, btl);
        kC<<<dim3(12, B), 256>>>(norm_g + l, Whl, bhl, Wql, bql, gml, btl,
                                 Wo + (long)l * 32 * DIM, bo + (long)l * DIM);
    }

    k_logits<<<BN / 16, 256, LOGITS_SMEM>>>(fg, Wl, bl);
    k_head<<<B, 256>>>(W1, b1, W2, b2, out);
    (void)in_sizes; (void)n_in; (void)out_size;
}

// round 13
// speedup vs baseline: 1.7929x; 1.0977x over previous
#include <cuda_runtime.h>
#include <math.h>

#define B 128
#define N 996
#define BN (B*N)
#define DIM 16
#define QKD 128
#define GSZ 256
#define NG 4
#define DEPTH 8
#define VOC 1024
#define ROTD 32

// ---------------- scratch ----------------
__device__ __align__(16) float g_x[BN*DIM];
__device__ __align__(16) float g_qo[BN*32];          // ungated quad attention out
__device__ __align__(16) float g_linkvp[B*8*128*32];
__device__ float g_rc[N*16];
__device__ float g_rs[N*16];
__device__ float g_hmax[BN];

#define ROT_LC 0.57564627324851142
#define POS_LC 1.1512925464970228

typedef unsigned long long ull;

__device__ __forceinline__ ull pk2(float a, float b) {
    ull r; asm("mov.b64 %0,{%1,%2};" : "=l"(r) : "f"(a), "f"(b)); return r;
}
__device__ __forceinline__ void fma2(ull& d, ull a, ull b) {
    asm("fma.rn.f32x2 %0,%1,%2,%0;" : "+l"(d) : "l"(a), "l"(b));
}
__device__ __forceinline__ float2 up2(ull v) {
    float2 f; asm("mov.b64 {%0,%1},%2;" : "=f"(f.x), "=f"(f.y) : "l"(v)); return f;
}
__device__ __forceinline__ float silu_f(float a) {
    return __fdividef(a, 1.0f + __expf(-a));
}

// proj 8 outputs [u0,u0+8) ; nmA = prev-token normed d0..7, nmB = cur normed d8..15
__device__ __forceinline__ void proj8(const float* nmA, const float* nmB,
                                      const float* __restrict__ W, int ws,
                                      const float* __restrict__ bias, int u0, float* o) {
    #pragma unroll
    for (int j = 0; j < 8; j++) o[j] = bias[u0 + j];
    #pragma unroll
    for (int d = 0; d < 8; d++) { float a = nmA[d];
        #pragma unroll
        for (int j = 0; j < 8; j++) o[j] += a * W[d * ws + u0 + j]; }
    #pragma unroll
    for (int d = 0; d < 8; d++) { float a = nmB[d];
        #pragma unroll
        for (int j = 0; j < 8; j++) o[j] += a * W[(d + 8) * ws + u0 + j]; }
}
// silu + gamma/beta + rotary (chunk-aligned); gb: [0..127]=gamma, [128..255]=beta
__device__ __forceinline__ void gbrot8(float* o, int u0, const float* __restrict__ gb, int pos) {
    #pragma unroll
    for (int jj = 0; jj < 8; jj++) o[jj] = silu_f(o[jj]);
    if (u0 < ROTD) {
        #pragma unroll
        for (int jj = 0; jj < 8; jj += 2) {
            int u = u0 + jj;
            float a = o[jj] * gb[u] + gb[128 + u];
            float b = o[jj+1] * gb[u+1] + gb[128 + u + 1];
            float c = g_rc[pos * 16 + (u >> 1)], s = g_rs[pos * 16 + (u >> 1)];
            o[jj] = a * c - b * s;
            o[jj+1] = b * c + a * s;
        }
    } else {
        #pragma unroll
        for (int jj = 0; jj < 8; jj++) { int u = u0 + jj; o[jj] = o[jj] * gb[u] + gb[128 + u]; }
    }
}

// ---------------- K0 / K0b ----------------
__global__ void k_embed(const int* __restrict__ kmer, const float* __restrict__ emb,
                        const float* __restrict__ ps) {
    int idx = blockIdx.x * blockDim.x + threadIdx.x;
    if (idx >= BN * DIM) return;
    int d = idx & 15;
    int tok = idx >> 4;
    int t = tok % N;
    int j = (d < 8) ? d : d - 8;
    float inv = (float)exp(-(double)j * POS_LC);
    float ang = (float)t * inv;
    float p = (d < 8) ? sinf(ang) : cosf(ang);
    g_x[idx] = emb[kmer[tok] * DIM + d] + p * ps[0];
}
__global__ void k_rot() {
    int idx = blockIdx.x * blockDim.x + threadIdx.x;
    if (idx >= N * 16) return;
    int t = idx >> 4, j = idx & 15;
    float inv = (float)exp(-(double)j * ROT_LC);
    float ang = (float)t * inv;
    g_rc[idx] = cosf(ang);
    g_rs[idx] = sinf(ang);
}

// ---------------- kA: fused norm+proj+quad attention + balanced lin-KV partial ----------------
#define OF_SN  0          // [257][17]
#define OF_QS  4372       // [128][132]
#define OF_KT  21268      // [128][66]  transposed K chunk
#define OF_AS  29716      // [128][66]
#define OF_VS  38164      // [64][34]
#define OF_WQK 40340      // [16][128]
#define OF_WV  42388      // [16][32]
#define OF_GBQ 42900      // gamma|beta quad_q
#define OF_GBK 43156      // gamma|beta quad_k
#define OF_BQK 43412
#define OF_BV  43540
#define OF_GB3 43572      // gamma|beta lin_k (row 3)
#define OF_LK  43828      // [64][132] lin_k chunk
#define KA_SMEM ((43828 + 8448) * 4)   // 209104 B

__global__ void __launch_bounds__(256, 1) kA(const float* __restrict__ ng,
        const float* __restrict__ Wh, const float* __restrict__ bh,
        const float* __restrict__ Wqk, const float* __restrict__ bqk,
        const float* __restrict__ gamma, const float* __restrict__ beta) {
    extern __shared__ float s[];
    float* SN = s + OF_SN;  float* QS = s + OF_QS;  float* KT = s + OF_KT;
    float* AS = s + OF_AS;  float* VS = s + OF_VS;  float* WQ = s + OF_WQK;
    float* WV = s + OF_WV;  float* GQ = s + OF_GBQ; float* GK = s + OF_GBK;
    float* BQ = s + OF_BQK; float* BV = s + OF_BV;  float* G3 = s + OF_GB3;
    float* LK = s + OF_LK;
    int tid = threadIdx.x;
    int qh = blockIdx.x, g = blockIdx.y, b = blockIdx.z;
    int gstart = g * GSZ;
    const int bN = b * N;

    for (int i = tid; i < 2048; i += 256) WQ[i] = Wqk[i];
    for (int i = tid; i < 512; i += 256) WV[i] = Wh[(i >> 5) * 64 + (i & 31)];
    if (tid < 128) {
        GQ[tid] = gamma[tid];       GQ[128 + tid] = beta[tid];
        GK[tid] = gamma[256 + tid]; GK[128 + tid] = beta[256 + tid];
        G3[tid] = gamma[384 + tid]; G3[128 + tid] = beta[384 + tid];
        BQ[tid] = bqk[tid];
    }
    if (tid < 32) BV[tid] = bh[tid];
    for (int i = tid; i < 257 * 4; i += 256) {
        int r = i >> 2, d4 = (i & 3) * 4;
        int p = gstart - 1 + r;
        float4 v = make_float4(0, 0, 0, 0);
        if (p >= 0 && p < N) v = *(const float4*)&g_x[(long)(bN + p) * 16 + d4];
        SN[r*17 + d4] = v.x; SN[r*17 + d4+1] = v.y; SN[r*17 + d4+2] = v.z; SN[r*17 + d4+3] = v.w;
    }
    __syncthreads();
    float gng = ng[0];
    for (int i = tid; i < 257; i += 256) {
        float ss = 0;
        #pragma unroll
        for (int d = 0; d < 16; d++) { float v = SN[i*17 + d]; ss += v * v; }
        float scl = gng / fmaxf(sqrtf(ss) * 0.25f, 1e-5f);
        #pragma unroll
        for (int d = 0; d < 16; d++) SN[i*17 + d] *= scl;
    }
    __syncthreads();

    {   // phase1: Q tile (128 q tokens x 128 dims)
        int j = tid >> 1, h = tid & 1;
        int p = gstart + qh * 128 + j;
        int si = qh * 128 + j + 1;
        float nmA[8], nmB[8];
        bool first = (p == 0);
        #pragma unroll
        for (int d = 0; d < 8; d++) {
            nmA[d] = first ? 0.0f : SN[(si - 1) * 17 + d];
            nmB[d] = SN[si * 17 + 8 + d];
        }
        int rp = (p < N) ? p : 0;
        #pragma unroll
        for (int c = 0; c < 8; c++) {
            int u0 = h * 64 + c * 8;
            float o[8];
            proj8(nmA, nmB, WQ, 128, BQ, u0, o);
            gbrot8(o, u0, GQ, rp);
            #pragma unroll
            for (int jj = 0; jj < 8; jj += 2)
                *(float2*)&QS[j * 132 + u0 + jj] = make_float2(o[jj], o[jj+1]);
        }
    }

    ull oacc[8];
    #pragma unroll
    for (int e = 0; e < 8; e++) oacc[e] = 0ull;
    ull lkacc[8];
    #pragma unroll
    for (int e = 0; e < 8; e++) lkacc[e] = 0ull;
    int oi = tid >> 1, eg = (tid & 1) * 16;
    int tx = tid & 7, ty = tid >> 3;
    int dd = tid & 127, e0v = (tid >> 7) * 16;

    for (int ck = 0; ck < 4; ck++) {
        bool mylin = (qh == (ck >> 1));   // each CTA owns 2 of the 4 chunks
        __syncthreads();
        {   // build K chunk (transposed) + V chunk + (owned) lin_k chunk
            int t = tid & 63, q4 = tid >> 6;
            int kloc = ck * 64 + t;
            int p = gstart + kloc;
            int si = kloc + 1;
            float nmA[8], nmB[8];
            bool first = (p == 0);
            #pragma unroll
            for (int d = 0; d < 8; d++) {
                nmA[d] = first ? 0.0f : SN[(si - 1) * 17 + d];
                nmB[d] = SN[si * 17 + 8 + d];
            }
            int rp = (p < N) ? p : 0;
            #pragma unroll
            for (int cc = 0; cc < 4; cc++) {
                int u0 = q4 * 32 + cc * 8;
                float o[8];
                proj8(nmA, nmB, WQ, 128, BQ, u0, o);
                gbrot8(o, u0, GK, rp);
                #pragma unroll
                for (int jj = 0; jj < 8; jj++) KT[(u0 + jj) * 66 + t] = o[jj];
            }
            {   int e0 = q4 * 8;
                float o[8];
                proj8(nmA, nmB, WV, 32, BV, e0, o);
                #pragma unroll
                for (int jj = 0; jj < 8; jj++) VS[t * 34 + e0 + jj] = silu_f(o[jj]);
            }
            if (mylin) {
                #pragma unroll
                for (int cc = 0; cc < 4; cc++) {
                    int u0 = q4 * 32 + cc * 8;
                    float o[8];
                    proj8(nmA, nmB, WQ, 128, BQ, u0, o);
                    gbrot8(o, u0, G3, rp);
                    #pragma unroll
                    for (int jj = 0; jj < 8; jj++)
                        LK[t * 132 + u0 + jj] = (p < N) ? o[jj] : 0.0f;
                }
            }
        }
        __syncthreads();
        {   // stage A: sim rows (4ty+r) x cols (2tx+16c)
            ull acc[4][4];
            #pragma unroll
            for (int r = 0; r < 4; r++)
                #pragma unroll
                for (int c = 0; c < 4; c++) acc[r][c] = 0ull;
            #pragma unroll 4
            for (int kk = 0; kk < 128; kk++) {
                ull kp[4];
                #pragma unroll
                for (int c = 0; c < 4; c++)
                    kp[c] = *(const ull*)&KT[kk * 66 + 2 * tx + 16 * c];
                #pragma unroll
                for (int r = 0; r < 4; r++) {
                    float qv = QS[(4 * ty + r) * 132 + kk];
                    ull qd = pk2(qv, qv);
                    #pragma unroll
                    for (int c = 0; c < 4; c++) fma2(acc[r][c], qd, kp[c]);
                }
            }
            int kb = gstart + ck * 64;
            #pragma unroll
            for (int r = 0; r < 4; r++) {
                int row = 4 * ty + r;
                #pragma unroll
                for (int c = 0; c < 4; c++) {
                    float2 f = up2(acc[r][c]);
                    int c0 = 2 * tx + 16 * c;
                    float s0 = fmaxf(f.x * (1.0f/256.0f), 0.0f); s0 *= s0;
                    float s1 = fmaxf(f.y * (1.0f/256.0f), 0.0f); s1 *= s1;
                    if (kb + c0     >= N) s0 = 0.0f;
                    if (kb + c0 + 1 >= N) s1 = 0.0f;
                    *(ull*)&AS[row * 66 + c0] = pk2(s0, s1);
                }
            }
        }
        __syncthreads();
        {   // stage B: O[oi][eg..eg+15] += A * V
            #pragma unroll 4
            for (int j = 0; j < 64; j++) {
                float a = AS[oi * 66 + j];
                ull ad = pk2(a, a);
                const ull* vp = (const ull*)&VS[j * 34 + eg];
                #pragma unroll
                for (int e = 0; e < 8; e++) fma2(oacc[e], ad, vp[e]);
            }
        }
        if (mylin) {   // lin-KV partial for owned chunk
            #pragma unroll 4
            for (int j = 0; j < 64; j++) {
                float lv = LK[j * 132 + dd];
                ull ld = pk2(lv, lv);
                const ull* vp = (const ull*)&VS[j * 34 + e0v];
                #pragma unroll
                for (int e = 0; e < 8; e++) fma2(lkacc[e], ld, vp[e]);
            }
        }
    }
    int qp = gstart + qh * 128 + oi;
    if (qp < N) {
        float* dst = &g_qo[(long)(bN + qp) * 32 + eg];
        #pragma unroll
        for (int e = 0; e < 8; e++) { float2 f = up2(oacc[e]); *(float2*)&dst[e * 2] = f; }
    }
    {   // one partial per (g, qh) pair
        float* dst = &g_linkvp[((long)(b * 8 + g * 2 + qh) * 128 + dd) * 32 + e0v];
        #pragma unroll
        for (int e = 0; e < 8; e++) { float2 f = up2(lkacc[e]); *(float2*)&dst[e * 2] = f; }
    }
}

// ---------------- kC: KV-reduce + lin_out (tiled, no shfl) + gate + Wo + residual ----------------
__global__ void __launch_bounds__(256, 2) kC(const float* __restrict__ ng,
        const float* __restrict__ Wh, const float* __restrict__ bh,
        const float* __restrict__ Wqk, const float* __restrict__ bqk,
        const float* __restrict__ gamma, const float* __restrict__ beta,
        const float* __restrict__ Wo, const float* __restrict__ bo) {
    __shared__ __align__(16) float SN[84 * 17];
    __shared__ __align__(16) float SKV[4096];
    __shared__ __align__(16) float WQ[2048];
    __shared__ __align__(16) float WG[512];
    __shared__ __align__(16) float GB[256];
    __shared__ __align__(16) float BQ2[128];
    __shared__ __align__(16) float BG[32];
    __shared__ __align__(16) float SWO[512];
    __shared__ __align__(16) float SBO[16];
    __shared__ __align__(16) float SLQ[32 * 132];
    __shared__ __align__(16) float SG[32 * 33];
    __shared__ __align__(16) float OV[32 * 34];
    int tid = threadIdx.x;
    int ch = blockIdx.x, b = blockIdx.y;
    const int bN = b * N;
    int t0 = ch * 83;

    for (int i = tid; i < 2048; i += 256) WQ[i] = Wqk[i];
    for (int i = tid; i < 512; i += 256) {
        WG[i] = Wh[(i >> 5) * 64 + 32 + (i & 31)];
        SWO[i] = Wo[i];
    }
    if (tid < 128) {
        GB[tid] = gamma[128 + tid]; GB[128 + tid] = beta[128 + tid];
        BQ2[tid] = bqk[tid];
    }
    if (tid < 32) BG[tid] = bh[32 + tid];
    if (tid < 16) SBO[tid] = bo[tid];
    const float inv_n = 1.0f / (float)N;
    for (int i = tid; i < 1024; i += 256) {
        float4 ssum = make_float4(0, 0, 0, 0);
        #pragma unroll
        for (int k2 = 0; k2 < 8; k2++) {
            float4 p = ((const float4*)&g_linkvp[(long)(b * 8 + k2) * 4096])[i];
            ssum.x += p.x; ssum.y += p.y; ssum.z += p.z; ssum.w += p.w;
        }
        ((float4*)SKV)[i] = make_float4(ssum.x * inv_n, ssum.y * inv_n, ssum.z * inv_n, ssum.w * inv_n);
    }
    for (int i = tid; i < 84 * 4; i += 256) {
        int r = i >> 2, d4 = (i & 3) * 4;
        int p = t0 - 1 + r;
        float4 v = make_float4(0, 0, 0, 0);
        if (p >= 0 && p < N) v = *(const float4*)&g_x[(long)(bN + p) * 16 + d4];
        SN[r*17 + d4] = v.x; SN[r*17 + d4+1] = v.y; SN[r*17 + d4+2] = v.z; SN[r*17 + d4+3] = v.w;
    }
    __syncthreads();
    float gng = ng[0];
    for (int i = tid; i < 84; i += 256) {
        float ss = 0;
        #pragma unroll
        for (int d = 0; d < 16; d++) { float v = SN[i*17 + d]; ss += v * v; }
        float scl = gng / fmaxf(sqrtf(ss) * 0.25f, 1e-5f);
        #pragma unroll
        for (int d = 0; d < 16; d++) SN[i*17 + d] *= scl;
    }

    int w = tid >> 5, lane = tid & 31;
    for (int tb = 0; tb < 96; tb += 32) {
        __syncthreads();   // SN norm done (first iter) / prior block's reads done
        // ---- P1: lq + gate for 32 tokens (warp w -> local tokens 4w..4w+3) ----
        #pragma unroll
        for (int i = 0; i < 4; i++) {
            int ltl = w * 4 + i;            // local in block
            int lt = tb + ltl;              // local in chunk
            int ltc = min(lt, 82);
            int tok = t0 + ltc;
            int si = ltc + 1;
            bool first = (tok == 0);
            float nmA[8], nmB[8];
            #pragma unroll
            for (int d = 0; d < 8; d++) {
                nmA[d] = first ? 0.0f : SN[(si - 1) * 17 + d];
                nmB[d] = SN[si * 17 + 8 + d];
            }
            #pragma unroll
            for (int j = 0; j < 4; j++) {
                int u = lane + 32 * j;
                float o = BQ2[u];
                #pragma unroll
                for (int d = 0; d < 8; d++) o += nmA[d] * WQ[d * 128 + u];
                #pragma unroll
                for (int d = 0; d < 8; d++) o += nmB[d] * WQ[(d + 8) * 128 + u];
                o = silu_f(o);
                o = o * GB[u] + GB[128 + u];
                if (j == 0) {
                    float c = g_rc[tok * 16 + (lane >> 1)], sn2 = g_rs[tok * 16 + (lane >> 1)];
                    float part = __shfl_xor_sync(0xffffffffu, o, 1);
                    o = (lane & 1) ? (o * c + part * sn2) : (o * c - part * sn2);
                }
                SLQ[ltl * 132 + u] = o;
            }
            {   float o = BG[lane];
                #pragma unroll
                for (int d = 0; d < 8; d++) o += nmA[d] * WG[d * 32 + lane];
                #pragma unroll
                for (int d = 0; d < 8; d++) o += nmB[d] * WG[(d + 8) * 32 + lane];
                SG[ltl * 33 + lane] = silu_f(o);
            }
        }
        __syncthreads();
        // ---- P2: lin_out tile: 32 tokens x 32 dims, thread = (tt, e-quad) ----
        {
            int tt = tid >> 3;          // 0..31 local token
            int e4 = (tid & 7) * 4;     // e-quad
            ull a0 = 0ull, a1 = 0ull, b0 = 0ull, b1 = 0ull;
            #pragma unroll 8
            for (int d = 0; d < 128; d += 2) {
                float q0 = SLQ[tt * 132 + d];
                float q1 = SLQ[tt * 132 + d + 1];
                ulonglong2 kv0 = *(const ulonglong2*)&SKV[d * 32 + e4];
                ulonglong2 kv1 = *(const ulonglong2*)&SKV[(d + 1) * 32 + e4];
                ull qd0 = pk2(q0, q0), qd1 = pk2(q1, q1);
                fma2(a0, qd0, kv0.x); fma2(a1, qd0, kv0.y);
                fma2(b0, qd1, kv1.x); fma2(b1, qd1, kv1.y);
            }
            float2 fa0 = up2(a0), fa1 = up2(a1), fb0 = up2(b0), fb1 = up2(b1);
            int lt = tb + tt;
            int ltc = min(lt, 82);
            int tok = t0 + ltc;
            float4 qo = *(const float4*)&g_qo[(long)(bN + tok) * 32 + e4];
            float g0 = SG[tt * 33 + e4],     g1 = SG[tt * 33 + e4 + 1];
            float g2 = SG[tt * 33 + e4 + 2], g3 = SG[tt * 33 + e4 + 3];
            OV[tt * 34 + e4]     = (qo.x + fa0.x + fb0.x) * g0;
            OV[tt * 34 + e4 + 1] = (qo.y + fa0.y + fb0.y) * g1;
            OV[tt * 34 + e4 + 2] = (qo.z + fa1.x + fb1.x) * g2;
            OV[tt * 34 + e4 + 3] = (qo.w + fa1.y + fb1.y) * g3;
        }
        __syncthreads();
        // ---- P3: Wo + residual: 16 tokens x 16 dims per half ----
        {
            int dcol = tid & 15;
            int tt2 = tid >> 4;   // 0..15
            #pragma unroll
            for (int h = 0; h < 2; h++) {
                int ttw = tt2 + 16 * h;
                int lt = tb + ttw;
                if (lt < 83) {
                    float y = SBO[dcol];
                    #pragma unroll
                    for (int e = 0; e < 32; e++) y += OV[ttw * 34 + e] * SWO[e * 16 + dcol];
                    g_x[(long)(bN + t0 + lt) * 16 + dcol] += y;
                }
            }
        }
    }
}

// ---------------- k_logits / k_head ----------------
#define LOGITS_SMEM ((16*1024 + 1024 + 16*16) * 4)
__global__ void k_logits(const float* __restrict__ fg, const float* __restrict__ Wl,
                         const float* __restrict__ blv) {
    extern __shared__ float sm[];
    float* sW = sm;
    float* sb = sW + 16 * 1024;
    float* xn = sb + 1024;
    __shared__ float wred[8];
    __shared__ float xs[16];
    int tid = threadIdx.x;
    int base = blockIdx.x * 16;
    for (int i = tid; i < (16 * 1024) / 4; i += 256)
        ((float4*)sW)[i] = ((const float4*)Wl)[i];
    for (int i = tid; i < 1024; i += 256) sb[i] = blv[i];
    {   int tt = tid >> 4, d = tid & 15;
        xn[tt * 16 + d] = g_x[(long)(base + tt) * DIM + d];
    }
    __syncthreads();
    if (tid < 16) {
        float ss = 0;
        #pragma unroll
        for (int d = 0; d < 16; d++) { float v = xn[tid * 16 + d]; ss += v * v; }
        xs[tid] = fg[0] / fmaxf(sqrtf(ss) * 0.25f, 1e-5f);
    }
    __syncthreads();
    {   int tt = tid >> 4, d = tid & 15;
        xn[tt * 16 + d] *= xs[tt];
    }
    __syncthreads();
    int warp = tid >> 5, lane = tid & 31;
    int v0 = tid * 4;
    for (int tt = 0; tt < 16; tt++) {
        float s0 = sb[v0], s1 = sb[v0+1], s2 = sb[v0+2], s3 = sb[v0+3];
        #pragma unroll
        for (int d = 0; d < 16; d++) {
            float xv = xn[tt * 16 + d];
            float4 wv = *(const float4*)&sW[d * 1024 + v0];
            s0 += xv * wv.x; s1 += xv * wv.y; s2 += xv * wv.z; s3 += xv * wv.w;
        }
        float m = fmaxf(fmaxf(s0, s1), fmaxf(s2, s3));
        #pragma unroll
        for (int off = 16; off > 0; off >>= 1)
            m = fmaxf(m, __shfl_xor_sync(0xffffffff, m, off));
        if (lane == 0) wred[warp] = m;
        __syncthreads();
        if (tid == 0) {
            float mm = wred[0];
            #pragma unroll
            for (int j = 1; j < 8; j++) mm = fmaxf(mm, wred[j]);
            g_hmax[base + tt] = mm;
        }
        __syncthreads();
    }
}
__global__ void k_head(const float* __restrict__ W1, const float* __restrict__ b1,
                       const float* __restrict__ W2, const float* __restrict__ b2,
                       float* __restrict__ out) {
    __shared__ float red[8][32];
    __shared__ float rr[32];
    int tid = threadIdx.x;
    int b = blockIdx.x;
    int col = tid & 31, seg = tid >> 5;
    float acc = 0.0f;
    int t0 = seg * 125;
    int t1 = min(t0 + 125, N);
    for (int t = t0; t < t1; t++)
        acc += g_hmax[(long)b * N + t] * W1[t * 32 + col];
    red[seg][col] = acc;
    __syncthreads();
    if (tid < 32) {
        float ss = b1[tid];
        #pragma unroll
        for (int k = 0; k < 8; k++) ss += red[k][tid];
        rr[tid] = fmaxf(ss, 0.0f);
    }
    __syncthreads();
    if (tid == 0) {
        float o = b2[0];
        #pragma unroll
        for (int j = 0; j < 32; j++) o += rr[j] * W2[j];
        out[b] = o;
    }
}

// ---------------- launch ----------------
extern "C" void kernel_launch(void* const* d_in, const int* in_sizes, int n_in,
                              void* d_out, int out_size) {
    const int*   kmer    = (const int*)  d_in[0];
    const float* emb     = (const float*)d_in[1];
    const float* psc     = (const float*)d_in[2];
    const float* norm_g  = (const float*)d_in[3];
    const float* Wh      = (const float*)d_in[4];
    const float* bh      = (const float*)d_in[5];
    const float* Wqk     = (const float*)d_in[6];
    const float* bqk     = (const float*)d_in[7];
    const float* gamma   = (const float*)d_in[8];
    const float* beta    = (const float*)d_in[9];
    const float* Wo      = (const float*)d_in[10];
    const float* bo      = (const float*)d_in[11];
    const float* fg      = (const float*)d_in[12];
    const float* Wl      = (const float*)d_in[13];
    const float* bl      = (const float*)d_in[14];
    const float* W1      = (const float*)d_in[15];
    const float* b1      = (const float*)d_in[16];
    const float* W2      = (const float*)d_in[17];
    const float* b2      = (const float*)d_in[18];
    float* out = (float*)d_out;

    cudaFuncSetAttribute(kA, cudaFuncAttributeMaxDynamicSharedMemorySize, KA_SMEM);
    cudaFuncSetAttribute(k_logits, cudaFuncAttributeMaxDynamicSharedMemorySize, LOGITS_SMEM);

    k_embed<<<(BN * DIM + 255) / 256, 256>>>(kmer, emb, psc);
    k_rot<<<(N * 16 + 255) / 256, 256>>>();

    for (int l = 0; l < DEPTH; l++) {
        const float* Whl = Wh + (long)l * 16 * 64;
        const float* bhl = bh + (long)l * 64;
        const float* Wql = Wqk + (long)l * 16 * 128;
        const float* bql = bqk + (long)l * 128;
        const float* gml = gamma + (long)l * 4 * 128;
        const float* btl = beta + (long)l * 4 * 128;
        kA<<<dim3(2, NG, B), 256, KA_SMEM>>>(norm_g + l, Whl, bhl, Wql, bql, gml, btl);
        kC<<<dim3(12, B), 256>>>(norm_g + l, Whl, bhl, Wql, bql, gml, btl,
                                 Wo + (long)l * 32 * DIM, bo + (long)l * DIM);
    }

    k_logits<<<BN / 16, 256, LOGITS_SMEM>>>(fg, Wl, bl);
    k_head<<<B, 256>>>(W1, b1, W2, b2, out);
    (void)in_sizes; (void)n_in; (void)out_size;
}

// round 14
// speedup vs baseline: 1.9838x; 1.1065x over previous
#include <cuda_runtime.h>
#include <math.h>

#define B 128
#define N 996
#define BN (B*N)
#define DIM 16
#define QKD 128
#define GSZ 256
#define NG 4
#define DEPTH 8
#define VOC 1024
#define ROTD 32

// ---------------- scratch ----------------
__device__ __align__(16) float g_x[BN*DIM];
__device__ __align__(16) float g_qo[BN*32];
__device__ __align__(16) float g_linkvp[B*8*128*32];
__device__ float g_rc[N*16];
__device__ float g_rs[N*16];
__device__ float g_hmax[BN];

#define ROT_LC 0.57564627324851142
#define POS_LC 1.1512925464970228

typedef unsigned long long ull;

__device__ __forceinline__ ull pk2(float a, float b) {
    ull r; asm("mov.b64 %0,{%1,%2};" : "=l"(r) : "f"(a), "f"(b)); return r;
}
__device__ __forceinline__ void fma2(ull& d, ull a, ull b) {
    asm("fma.rn.f32x2 %0,%1,%2,%0;" : "+l"(d) : "l"(a), "l"(b));
}
__device__ __forceinline__ float2 up2(ull v) {
    float2 f; asm("mov.b64 {%0,%1},%2;" : "=f"(f.x), "=f"(f.y) : "l"(v)); return f;
}
__device__ __forceinline__ float silu_f(float a) {
    return __fdividef(a, 1.0f + __expf(-a));
}
__device__ __forceinline__ unsigned f2tf(float f) {
    unsigned r; asm("cvt.rna.tf32.f32 %0,%1;" : "=r"(r) : "f"(f)); return r;
}
__device__ __forceinline__ void mma8(float* c, const unsigned* a, unsigned b0, unsigned b1) {
    asm volatile("mma.sync.aligned.m16n8k8.row.col.f32.tf32.tf32.f32 "
                 "{%0,%1,%2,%3},{%4,%5,%6,%7},{%8,%9},{%0,%1,%2,%3};"
                 : "+f"(c[0]), "+f"(c[1]), "+f"(c[2]), "+f"(c[3])
                 : "r"(a[0]), "r"(a[1]), "r"(a[2]), "r"(a[3]), "r"(b0), "r"(b1));
}

// proj 8 outputs [u0,u0+8)
__device__ __forceinline__ void proj8(const float* nmA, const float* nmB,
                                      const float* __restrict__ W, int ws,
                                      const float* __restrict__ bias, int u0, float* o) {
    #pragma unroll
    for (int j = 0; j < 8; j++) o[j] = bias[u0 + j];
    #pragma unroll
    for (int d = 0; d < 8; d++) { float a = nmA[d];
        #pragma unroll
        for (int j = 0; j < 8; j++) o[j] += a * W[d * ws + u0 + j]; }
    #pragma unroll
    for (int d = 0; d < 8; d++) { float a = nmB[d];
        #pragma unroll
        for (int j = 0; j < 8; j++) o[j] += a * W[(d + 8) * ws + u0 + j]; }
}
__device__ __forceinline__ void gbrot8(float* o, int u0, const float* __restrict__ gb, int pos) {
    #pragma unroll
    for (int jj = 0; jj < 8; jj++) o[jj] = silu_f(o[jj]);
    if (u0 < ROTD) {
        #pragma unroll
        for (int jj = 0; jj < 8; jj += 2) {
            int u = u0 + jj;
            float a = o[jj] * gb[u] + gb[128 + u];
            float b = o[jj+1] * gb[u+1] + gb[128 + u + 1];
            float c = g_rc[pos * 16 + (u >> 1)], s = g_rs[pos * 16 + (u >> 1)];
            o[jj] = a * c - b * s;
            o[jj+1] = b * c + a * s;
        }
    } else {
        #pragma unroll
        for (int jj = 0; jj < 8; jj++) { int u = u0 + jj; o[jj] = o[jj] * gb[u] + gb[128 + u]; }
    }
}

// ---------------- K0 / K0b ----------------
__global__ void k_embed(const int* __restrict__ kmer, const float* __restrict__ emb,
                        const float* __restrict__ ps) {
    int idx = blockIdx.x * blockDim.x + threadIdx.x;
    if (idx >= BN * DIM) return;
    int d = idx & 15;
    int tok = idx >> 4;
    int t = tok % N;
    int j = (d < 8) ? d : d - 8;
    float inv = (float)exp(-(double)j * POS_LC);
    float ang = (float)t * inv;
    float p = (d < 8) ? sinf(ang) : cosf(ang);
    g_x[idx] = emb[kmer[tok] * DIM + d] + p * ps[0];
}
__global__ void k_rot() {
    int idx = blockIdx.x * blockDim.x + threadIdx.x;
    if (idx >= N * 16) return;
    int t = idx >> 4, j = idx & 15;
    float inv = (float)exp(-(double)j * ROT_LC);
    float ang = (float)t * inv;
    g_rc[idx] = cosf(ang);
    g_rs[idx] = sinf(ang);
}

// ---------------- kA: fused norm+proj + tf32-mma quad attention + lin-KV partial ----------------
#define OF_SN  0          // [257][17] -> 4369, pad 4372
#define OF_QS  4372       // [128][132] fp32
#define OF_KTH 21268      // [128][72] tf32 hi (u32)
#define OF_KTL 30484      // [128][72] tf32 lo
#define OF_VS  39700      // [64][40] fp32
#define OF_WQK 42260      // 2048
#define OF_WV  44308      // 512
#define OF_GBQ 44820      // 256
#define OF_GBK 45076      // 256
#define OF_BQK 45332      // 128
#define OF_BV  45460      // 32
#define OF_GB3 45492      // 256
#define OF_LK  45748      // [64][136]
#define KA_SMEM ((45748 + 8704 + 12) * 4)   // 217856 B

__global__ void __launch_bounds__(256, 1) kA(const float* __restrict__ ng,
        const float* __restrict__ Wh, const float* __restrict__ bh,
        const float* __restrict__ Wqk, const float* __restrict__ bqk,
        const float* __restrict__ gamma, const float* __restrict__ beta) {
    extern __shared__ float s[];
    float* SN = s + OF_SN;  float* QS = s + OF_QS;
    unsigned* KTH = (unsigned*)(s + OF_KTH);
    unsigned* KTL = (unsigned*)(s + OF_KTL);
    float* VS = s + OF_VS;  float* WQ = s + OF_WQK;
    float* WV = s + OF_WV;  float* GQ = s + OF_GBQ; float* GK = s + OF_GBK;
    float* BQ = s + OF_BQK; float* BV = s + OF_BV;  float* G3 = s + OF_GB3;
    float* LK = s + OF_LK;
    int tid = threadIdx.x;
    int lane = tid & 31, wid = tid >> 5;
    int r8 = lane >> 2, t4 = lane & 3;
    int qh = blockIdx.x, g = blockIdx.y, b = blockIdx.z;
    int gstart = g * GSZ;
    const int bN = b * N;

    for (int i = tid; i < 2048; i += 256) WQ[i] = Wqk[i];
    for (int i = tid; i < 512; i += 256) WV[i] = Wh[(i >> 5) * 64 + (i & 31)];
    if (tid < 128) {
        GQ[tid] = gamma[tid];       GQ[128 + tid] = beta[tid];
        GK[tid] = gamma[256 + tid]; GK[128 + tid] = beta[256 + tid];
        G3[tid] = gamma[384 + tid]; G3[128 + tid] = beta[384 + tid];
        BQ[tid] = bqk[tid];
    }
    if (tid < 32) BV[tid] = bh[tid];
    for (int i = tid; i < 257 * 4; i += 256) {
        int r = i >> 2, d4 = (i & 3) * 4;
        int p = gstart - 1 + r;
        float4 v = make_float4(0, 0, 0, 0);
        if (p >= 0 && p < N) v = *(const float4*)&g_x[(long)(bN + p) * 16 + d4];
        SN[r*17 + d4] = v.x; SN[r*17 + d4+1] = v.y; SN[r*17 + d4+2] = v.z; SN[r*17 + d4+3] = v.w;
    }
    __syncthreads();
    float gng = ng[0];
    for (int i = tid; i < 257; i += 256) {
        float ss = 0;
        #pragma unroll
        for (int d = 0; d < 16; d++) { float v = SN[i*17 + d]; ss += v * v; }
        float scl = gng / fmaxf(sqrtf(ss) * 0.25f, 1e-5f);
        #pragma unroll
        for (int d = 0; d < 16; d++) SN[i*17 + d] *= scl;
    }
    __syncthreads();

    {   // Q tile (128 q tokens x 128 dims) fp32
        int j = tid >> 1, h = tid & 1;
        int p = gstart + qh * 128 + j;
        int si = qh * 128 + j + 1;
        float nmA[8], nmB[8];
        bool first = (p == 0);
        #pragma unroll
        for (int d = 0; d < 8; d++) {
            nmA[d] = first ? 0.0f : SN[(si - 1) * 17 + d];
            nmB[d] = SN[si * 17 + 8 + d];
        }
        int rp = (p < N) ? p : 0;
        #pragma unroll
        for (int c = 0; c < 8; c++) {
            int u0 = h * 64 + c * 8;
            float o[8];
            proj8(nmA, nmB, WQ, 128, BQ, u0, o);
            gbrot8(o, u0, GQ, rp);
            #pragma unroll
            for (int jj = 0; jj < 8; jj += 2)
                *(float2*)&QS[j * 132 + u0 + jj] = make_float2(o[jj], o[jj+1]);
        }
    }

    float co[4][4];           // AV accumulators (mma c-frags), accumulate across chunks
    #pragma unroll
    for (int a = 0; a < 4; a++)
        #pragma unroll
        for (int i = 0; i < 4; i++) co[a][i] = 0.0f;
    ull lkacc[8];
    #pragma unroll
    for (int e = 0; e < 8; e++) lkacc[e] = 0ull;
    int dd = tid & 127, e0v = (tid >> 7) * 16;
    int mrow = wid * 16 + r8;

    for (int ck = 0; ck < 4; ck++) {
        bool mylin = (qh == (ck >> 1));
        __syncthreads();
        {   // build K chunk tf32 hi/lo + V chunk + (owned) lin_k chunk
            int t = tid & 63, q4 = tid >> 6;
            int kloc = ck * 64 + t;
            int p = gstart + kloc;
            int si = kloc + 1;
            float nmA[8], nmB[8];
            bool first = (p == 0);
            #pragma unroll
            for (int d = 0; d < 8; d++) {
                nmA[d] = first ? 0.0f : SN[(si - 1) * 17 + d];
                nmB[d] = SN[si * 17 + 8 + d];
            }
            int rp = (p < N) ? p : 0;
            #pragma unroll
            for (int cc = 0; cc < 4; cc++) {
                int u0 = q4 * 32 + cc * 8;
                float o[8];
                proj8(nmA, nmB, WQ, 128, BQ, u0, o);
                gbrot8(o, u0, GK, rp);
                #pragma unroll
                for (int jj = 0; jj < 8; jj++) {
                    unsigned h2 = f2tf(o[jj]);
                    KTH[(u0 + jj) * 72 + t] = h2;
                    KTL[(u0 + jj) * 72 + t] = f2tf(o[jj] - __uint_as_float(h2));
                }
            }
            {   int e0 = q4 * 8;
                float o[8];
                proj8(nmA, nmB, WV, 32, BV, e0, o);
                #pragma unroll
                for (int jj = 0; jj < 8; jj++) VS[t * 40 + e0 + jj] = silu_f(o[jj]);
            }
            if (mylin) {
                #pragma unroll
                for (int cc = 0; cc < 4; cc++) {
                    int u0 = q4 * 32 + cc * 8;
                    float o[8];
                    proj8(nmA, nmB, WQ, 128, BQ, u0, o);
                    gbrot8(o, u0, G3, rp);
                    #pragma unroll
                    for (int jj = 0; jj < 8; jj++)
                        LK[t * 136 + u0 + jj] = (p < N) ? o[jj] : 0.0f;
                }
            }
        }
        __syncthreads();

        // ---- sim via tf32 mma: warp owns rows [wid*16, wid*16+16), 64 keys ----
        float cs[8][4];
        #pragma unroll
        for (int nt = 0; nt < 8; nt++)
            #pragma unroll
            for (int i = 0; i < 4; i++) cs[nt][i] = 0.0f;
        #pragma unroll 2
        for (int kt = 0; kt < 16; kt++) {
            int kc0 = kt * 8 + t4;
            float q0 = QS[mrow * 132 + kc0];
            float q1 = QS[(mrow + 8) * 132 + kc0];
            float q2 = QS[mrow * 132 + kc0 + 4];
            float q3 = QS[(mrow + 8) * 132 + kc0 + 4];
            unsigned ah[4], al[4];
            ah[0] = f2tf(q0); al[0] = f2tf(q0 - __uint_as_float(ah[0]));
            ah[1] = f2tf(q1); al[1] = f2tf(q1 - __uint_as_float(ah[1]));
            ah[2] = f2tf(q2); al[2] = f2tf(q2 - __uint_as_float(ah[2]));
            ah[3] = f2tf(q3); al[3] = f2tf(q3 - __uint_as_float(ah[3]));
            #pragma unroll
            for (int nt = 0; nt < 8; nt++) {
                unsigned bh0 = KTH[kc0 * 72 + nt * 8 + r8];
                unsigned bh1 = KTH[(kc0 + 4) * 72 + nt * 8 + r8];
                unsigned bl0 = KTL[kc0 * 72 + nt * 8 + r8];
                unsigned bl1 = KTL[(kc0 + 4) * 72 + nt * 8 + r8];
                mma8(cs[nt], ah, bh0, bh1);
                mma8(cs[nt], ah, bl0, bl1);
                mma8(cs[nt], al, bh0, bh1);
            }
        }
        // ---- epilogue: relu^2 mask -> tf32 A-frags (R4 shuffle) -> A@V mma ----
        {   int kb = gstart + ck * 64;
            #pragma unroll
            for (int nt = 0; nt < 8; nt++) {
                int col0 = kb + nt * 8 + 2 * t4;
                float e00 = fmaxf(cs[nt][0] * (1.0f/256.0f), 0.0f); e00 *= e00;
                float e01 = fmaxf(cs[nt][1] * (1.0f/256.0f), 0.0f); e01 *= e01;
                float e10 = fmaxf(cs[nt][2] * (1.0f/256.0f), 0.0f); e10 *= e10;
                float e11 = fmaxf(cs[nt][3] * (1.0f/256.0f), 0.0f); e11 *= e11;
                if (col0     >= N) { e00 = 0.0f; e10 = 0.0f; }
                if (col0 + 1 >= N) { e01 = 0.0f; e11 = 0.0f; }
                unsigned u00 = f2tf(e00), u01 = f2tf(e01);
                unsigned u10 = f2tf(e10), u11 = f2tf(e11);
                int srcA = (lane & ~3) | (t4 >> 1);
                int srcB = srcA + 2;
                unsigned w00A = __shfl_sync(0xffffffffu, u00, srcA);
                unsigned w01A = __shfl_sync(0xffffffffu, u01, srcA);
                unsigned w10A = __shfl_sync(0xffffffffu, u10, srcA);
                unsigned w11A = __shfl_sync(0xffffffffu, u11, srcA);
                unsigned w00B = __shfl_sync(0xffffffffu, u00, srcB);
                unsigned w01B = __shfl_sync(0xffffffffu, u01, srcB);
                unsigned w10B = __shfl_sync(0xffffffffu, u10, srcB);
                unsigned w11B = __shfl_sync(0xffffffffu, u11, srcB);
                bool odd = (t4 & 1);
                unsigned aF[4];
                aF[0] = odd ? w01A : w00A;
                aF[1] = odd ? w11A : w10A;
                aF[2] = odd ? w01B : w00B;
                aF[3] = odd ? w11B : w10B;
                #pragma unroll
                for (int av = 0; av < 4; av++) {
                    float v0 = VS[(nt * 8 + t4) * 40 + av * 8 + r8];
                    float v1 = VS[(nt * 8 + t4 + 4) * 40 + av * 8 + r8];
                    unsigned bh0 = f2tf(v0), bh1 = f2tf(v1);
                    unsigned bl0 = f2tf(v0 - __uint_as_float(bh0));
                    unsigned bl1 = f2tf(v1 - __uint_as_float(bh1));
                    mma8(co[av], aF, bh0, bh1);
                    mma8(co[av], aF, bl0, bl1);
                }
            }
        }
        if (mylin) {
            #pragma unroll 4
            for (int j = 0; j < 64; j++) {
                float lv = LK[j * 136 + dd];
                ull ld = pk2(lv, lv);
                const ull* vp = (const ull*)&VS[j * 40 + e0v];
                #pragma unroll
                for (int e = 0; e < 8; e++) fma2(lkacc[e], ld, vp[e]);
            }
        }
    }
    {   // write quad out from c-frags
        int qp0 = gstart + qh * 128 + mrow;
        #pragma unroll
        for (int av = 0; av < 4; av++) {
            if (qp0 < N)
                *(float2*)&g_qo[(long)(bN + qp0) * 32 + av * 8 + 2 * t4] =
                    make_float2(co[av][0], co[av][1]);
            if (qp0 + 8 < N)
                *(float2*)&g_qo[(long)(bN + qp0 + 8) * 32 + av * 8 + 2 * t4] =
                    make_float2(co[av][2], co[av][3]);
        }
    }
    {   // one lin partial per (g, qh)
        float* dst = &g_linkvp[((long)(b * 8 + g * 2 + qh) * 128 + dd) * 32 + e0v];
        #pragma unroll
        for (int e = 0; e < 8; e++) { float2 f = up2(lkacc[e]); *(float2*)&dst[e * 2] = f; }
    }
}

// ---------------- kC: KV-reduce + lin_out (tiled) + gate + Wo + residual ----------------
__global__ void __launch_bounds__(256, 2) kC(const float* __restrict__ ng,
        const float* __restrict__ Wh, const float* __restrict__ bh,
        const float* __restrict__ Wqk, const float* __restrict__ bqk,
        const float* __restrict__ gamma, const float* __restrict__ beta,
        const float* __restrict__ Wo, const float* __restrict__ bo) {
    __shared__ __align__(16) float SN[84 * 17];
    __shared__ __align__(16) float SKV[4096];
    __shared__ __align__(16) float WQ[2048];
    __shared__ __align__(16) float WG[512];
    __shared__ __align__(16) float GB[256];
    __shared__ __align__(16) float BQ2[128];
    __shared__ __align__(16) float BG[32];
    __shared__ __align__(16) float SWO[512];
    __shared__ __align__(16) float SBO[16];
    __shared__ __align__(16) float SLQ[32 * 132];
    __shared__ __align__(16) float SG[32 * 33];
    __shared__ __align__(16) float OV[32 * 34];
    int tid = threadIdx.x;
    int ch = blockIdx.x, b = blockIdx.y;
    const int bN = b * N;
    int t0 = ch * 83;

    for (int i = tid; i < 2048; i += 256) WQ[i] = Wqk[i];
    for (int i = tid; i < 512; i += 256) {
        WG[i] = Wh[(i >> 5) * 64 + 32 + (i & 31)];
        SWO[i] = Wo[i];
    }
    if (tid < 128) {
        GB[tid] = gamma[128 + tid]; GB[128 + tid] = beta[128 + tid];
        BQ2[tid] = bqk[tid];
    }
    if (tid < 32) BG[tid] = bh[32 + tid];
    if (tid < 16) SBO[tid] = bo[tid];
    const float inv_n = 1.0f / (float)N;
    for (int i = tid; i < 1024; i += 256) {
        float4 ssum = make_float4(0, 0, 0, 0);
        #pragma unroll
        for (int k2 = 0; k2 < 8; k2++) {
            float4 p = ((const float4*)&g_linkvp[(long)(b * 8 + k2) * 4096])[i];
            ssum.x += p.x; ssum.y += p.y; ssum.z += p.z; ssum.w += p.w;
        }
        ((float4*)SKV)[i] = make_float4(ssum.x * inv_n, ssum.y * inv_n, ssum.z * inv_n, ssum.w * inv_n);
    }
    for (int i = tid; i < 84 * 4; i += 256) {
        int r = i >> 2, d4 = (i & 3) * 4;
        int p = t0 - 1 + r;
        float4 v = make_float4(0, 0, 0, 0);
        if (p >= 0 && p < N) v = *(const float4*)&g_x[(long)(bN + p) * 16 + d4];
        SN[r*17 + d4] = v.x; SN[r*17 + d4+1] = v.y; SN[r*17 + d4+2] = v.z; SN[r*17 + d4+3] = v.w;
    }
    __syncthreads();
    float gng = ng[0];
    for (int i = tid; i < 84; i += 256) {
        float ss = 0;
        #pragma unroll
        for (int d = 0; d < 16; d++) { float v = SN[i*17 + d]; ss += v * v; }
        float scl = gng / fmaxf(sqrtf(ss) * 0.25f, 1e-5f);
        #pragma unroll
        for (int d = 0; d < 16; d++) SN[i*17 + d] *= scl;
    }

    int w = tid >> 5, lane = tid & 31;
    for (int tb = 0; tb < 96; tb += 32) {
        __syncthreads();
        #pragma unroll
        for (int i = 0; i < 4; i++) {
            int ltl = w * 4 + i;
            int lt = tb + ltl;
            int ltc = min(lt, 82);
            int tok = t0 + ltc;
            int si = ltc + 1;
            bool first = (tok == 0);
            float nmA[8], nmB[8];
            #pragma unroll
            for (int d = 0; d < 8; d++) {
                nmA[d] = first ? 0.0f : SN[(si - 1) * 17 + d];
                nmB[d] = SN[si * 17 + 8 + d];
            }
            #pragma unroll
            for (int j = 0; j < 4; j++) {
                int u = lane + 32 * j;
                float o = BQ2[u];
                #pragma unroll
                for (int d = 0; d < 8; d++) o += nmA[d] * WQ[d * 128 + u];
                #pragma unroll
                for (int d = 0; d < 8; d++) o += nmB[d] * WQ[(d + 8) * 128 + u];
                o = silu_f(o);
                o = o * GB[u] + GB[128 + u];
                if (j == 0) {
                    float c = g_rc[tok * 16 + (lane >> 1)], sn2 = g_rs[tok * 16 + (lane >> 1)];
                    float part = __shfl_xor_sync(0xffffffffu, o, 1);
                    o = (lane & 1) ? (o * c + part * sn2) : (o * c - part * sn2);
                }
                SLQ[ltl * 132 + u] = o;
            }
            {   float o = BG[lane];
                #pragma unroll
                for (int d = 0; d < 8; d++) o += nmA[d] * WG[d * 32 + lane];
                #pragma unroll
                for (int d = 0; d < 8; d++) o += nmB[d] * WG[(d + 8) * 32 + lane];
                SG[ltl * 33 + lane] = silu_f(o);
            }
        }
        __syncthreads();
        {
            int tt = tid >> 3;
            int e4 = (tid & 7) * 4;
            ull a0 = 0ull, a1 = 0ull, b0 = 0ull, b1 = 0ull;
            #pragma unroll 8
            for (int d = 0; d < 128; d += 2) {
                float q0 = SLQ[tt * 132 + d];
                float q1 = SLQ[tt * 132 + d + 1];
                ulonglong2 kv0 = *(const ulonglong2*)&SKV[d * 32 + e4];
                ulonglong2 kv1 = *(const ulonglong2*)&SKV[(d + 1) * 32 + e4];
                ull qd0 = pk2(q0, q0), qd1 = pk2(q1, q1);
                fma2(a0, qd0, kv0.x); fma2(a1, qd0, kv0.y);
                fma2(b0, qd1, kv1.x); fma2(b1, qd1, kv1.y);
            }
            float2 fa0 = up2(a0), fa1 = up2(a1), fb0 = up2(b0), fb1 = up2(b1);
            int lt = tb + tt;
            int ltc = min(lt, 82);
            int tok = t0 + ltc;
            float4 qo = *(const float4*)&g_qo[(long)(bN + tok) * 32 + e4];
            float g0 = SG[tt * 33 + e4],     g1 = SG[tt * 33 + e4 + 1];
            float g2 = SG[tt * 33 + e4 + 2], g3 = SG[tt * 33 + e4 + 3];
            OV[tt * 34 + e4]     = (qo.x + fa0.x + fb0.x) * g0;
            OV[tt * 34 + e4 + 1] = (qo.y + fa0.y + fb0.y) * g1;
            OV[tt * 34 + e4 + 2] = (qo.z + fa1.x + fb1.x) * g2;
            OV[tt * 34 + e4 + 3] = (qo.w + fa1.y + fb1.y) * g3;
        }
        __syncthreads();
        {
            int dcol = tid & 15;
            int tt2 = tid >> 4;
            #pragma unroll
            for (int h = 0; h < 2; h++) {
                int ttw = tt2 + 16 * h;
                int lt = tb + ttw;
                if (lt < 83) {
                    float y = SBO[dcol];
                    #pragma unroll
                    for (int e = 0; e < 32; e++) y += OV[ttw * 34 + e] * SWO[e * 16 + dcol];
                    g_x[(long)(bN + t0 + lt) * 16 + dcol] += y;
                }
            }
        }
    }
}

// ---------------- k_logits / k_head ----------------
#define LOGITS_SMEM ((16*1024 + 1024 + 16*16) * 4)
__global__ void k_logits(const float* __restrict__ fg, const float* __restrict__ Wl,
                         const float* __restrict__ blv) {
    extern __shared__ float sm[];
    float* sW = sm;
    float* sb = sW + 16 * 1024;
    float* xn = sb + 1024;
    __shared__ float wred[8];
    __shared__ float xs[16];
    int tid = threadIdx.x;
    int base = blockIdx.x * 16;
    for (int i = tid; i < (16 * 1024) / 4; i += 256)
        ((float4*)sW)[i] = ((const float4*)Wl)[i];
    for (int i = tid; i < 1024; i += 256) sb[i] = blv[i];
    {   int tt = tid >> 4, d = tid & 15;
        xn[tt * 16 + d] = g_x[(long)(base + tt) * DIM + d];
    }
    __syncthreads();
    if (tid < 16) {
        float ss = 0;
        #pragma unroll
        for (int d = 0; d < 16; d++) { float v = xn[tid * 16 + d]; ss += v * v; }
        xs[tid] = fg[0] / fmaxf(sqrtf(ss) * 0.25f, 1e-5f);
    }
    __syncthreads();
    {   int tt = tid >> 4, d = tid & 15;
        xn[tt * 16 + d] *= xs[tt];
    }
    __syncthreads();
    int warp = tid >> 5, lane = tid & 31;
    int v0 = tid * 4;
    for (int tt = 0; tt < 16; tt++) {
        float s0 = sb[v0], s1 = sb[v0+1], s2 = sb[v0+2], s3 = sb[v0+3];
        #pragma unroll
        for (int d = 0; d < 16; d++) {
            float xv = xn[tt * 16 + d];
            float4 wv = *(const float4*)&sW[d * 1024 + v0];
            s0 += xv * wv.x; s1 += xv * wv.y; s2 += xv * wv.z; s3 += xv * wv.w;
        }
        float m = fmaxf(fmaxf(s0, s1), fmaxf(s2, s3));
        #pragma unroll
        for (int off = 16; off > 0; off >>= 1)
            m = fmaxf(m, __shfl_xor_sync(0xffffffff, m, off));
        if (lane == 0) wred[warp] = m;
        __syncthreads();
        if (tid == 0) {
            float mm = wred[0];
            #pragma unroll
            for (int j = 1; j < 8; j++) mm = fmaxf(mm, wred[j]);
            g_hmax[base + tt] = mm;
        }
        __syncthreads();
    }
}
__global__ void k_head(const float* __restrict__ W1, const float* __restrict__ b1,
                       const float* __restrict__ W2, const float* __restrict__ b2,
                       float* __restrict__ out) {
    __shared__ float red[8][32];
    __shared__ float rr[32];
    int tid = threadIdx.x;
    int b = blockIdx.x;
    int col = tid & 31, seg = tid >> 5;
    float acc = 0.0f;
    int t0 = seg * 125;
    int t1 = min(t0 + 125, N);
    for (int t = t0; t < t1; t++)
        acc += g_hmax[(long)b * N + t] * W1[t * 32 + col];
    red[seg][col] = acc;
    __syncthreads();
    if (tid < 32) {
        float ss = b1[tid];
        #pragma unroll
        for (int k = 0; k < 8; k++) ss += red[k][tid];
        rr[tid] = fmaxf(ss, 0.0f);
    }
    __syncthreads();
    if (tid == 0) {
        float o = b2[0];
        #pragma unroll
        for (int j = 0; j < 32; j++) o += rr[j] * W2[j];
        out[b] = o;
    }
}

// ---------------- launch ----------------
extern "C" void kernel_launch(void* const* d_in, const int* in_sizes, int n_in,
                              void* d_out, int out_size) {
    const int*   kmer    = (const int*)  d_in[0];
    const float* emb     = (const float*)d_in[1];
    const float* psc     = (const float*)d_in[2];
    const float* norm_g  = (const float*)d_in[3];
    const float* Wh      = (const float*)d_in[4];
    const float* bh      = (const float*)d_in[5];
    const float* Wqk     = (const float*)d_in[6];
    const float* bqk     = (const float*)d_in[7];
    const float* gamma   = (const float*)d_in[8];
    const float* beta    = (const float*)d_in[9];
    const float* Wo      = (const float*)d_in[10];
    const float* bo      = (const float*)d_in[11];
    const float* fg      = (const float*)d_in[12];
    const float* Wl      = (const float*)d_in[13];
    const float* bl      = (const float*)d_in[14];
    const float* W1      = (const float*)d_in[15];
    const float* b1      = (const float*)d_in[16];
    const float* W2      = (const float*)d_in[17];
    const float* b2      = (const float*)d_in[18];
    float* out = (float*)d_out;

    cudaFuncSetAttribute(kA, cudaFuncAttributeMaxDynamicSharedMemorySize, KA_SMEM);
    cudaFuncSetAttribute(k_logits, cudaFuncAttributeMaxDynamicSharedMemorySize, LOGITS_SMEM);

    k_embed<<<(BN * DIM + 255) / 256, 256>>>(kmer, emb, psc);
    k_rot<<<(N * 16 + 255) / 256, 256>>>();

    for (int l = 0; l < DEPTH; l++) {
        const float* Whl = Wh + (long)l * 16 * 64;
        const float* bhl = bh + (long)l * 64;
        const float* Wql = Wqk + (long)l * 16 * 128;
        const float* bql = bqk + (long)l * 128;
        const float* gml = gamma + (long)l * 4 * 128;
        const float* btl = beta + (long)l * 4 * 128;
        kA<<<dim3(2, NG, B), 256, KA_SMEM>>>(norm_g + l, Whl, bhl, Wql, bql, gml, btl);
        kC<<<dim3(12, B), 256>>>(norm_g + l, Whl, bhl, Wql, bql, gml, btl,
                                 Wo + (long)l * 32 * DIM, bo + (long)l * DIM);
    }

    k_logits<<<BN / 16, 256, LOGITS_SMEM>>>(fg, Wl, bl);
    k_head<<<B, 256>>>(W1, b1, W2, b2, out);
    (void)in_sizes; (void)n_in; (void)out_size;
}